// round 3
// baseline (speedup 1.0000x reference)
#include <cuda_runtime.h>
#include <cstddef>

#define Nn 10000
#define Ee 320000
#define Uu 256
#define Ll 3

#define BM 128
#define BN 128
#define BK 16
#define AS_LD 136

// ---------------- scratch (device globals; no allocations allowed) ----------
__device__ float g_x[Nn * Uu];
__device__ float g_xW1[Nn * Uu];
__device__ float g_xW2[Nn * Uu];
__device__ float g_xWs[Nn * Uu];
__device__ float g_xWt[Nn * Uu];
__device__ float g_agg[Nn * Uu];
__device__ float g_e0[(size_t)Ee * Uu];
__device__ float g_e1[(size_t)Ee * Uu];

// ---------------- shared SGEMM mainloop ------------------------------------
// C tile = A[row0:row0+128, :K] @ B[:K, col0:col0+128]
// A is row-major with ldA = K. B is row-major with ldB given.
__device__ __forceinline__ void gemm_mainloop(
    const float* __restrict__ A, const float* __restrict__ B,
    int M, int K, int ldB, int row0, int col0,
    float (*As)[AS_LD], float (*Bs)[BN], float acc[8][8])
{
    const int tid = threadIdx.x;
    const int tx = tid & 15, ty = tid >> 4;
    for (int k0 = 0; k0 < K; k0 += BK) {
#pragma unroll
        for (int v = 0; v < 2; v++) {
            int idx = tid + v * 256;
            // A tile: 128 rows x 16 k, float4 along k, transposed into As[k][m]
            int ar = idx >> 2;
            int ak = (idx & 3) << 2;
            int grow = row0 + ar;
            float4 av = make_float4(0.f, 0.f, 0.f, 0.f);
            if (grow < M)
                av = *(const float4*)(A + (size_t)grow * K + k0 + ak);
            As[ak + 0][ar] = av.x;
            As[ak + 1][ar] = av.y;
            As[ak + 2][ar] = av.z;
            As[ak + 3][ar] = av.w;
            // B tile: 16 rows x 128 cols, float4 along cols
            int br = idx >> 5;
            int bc = (idx & 31) << 2;
            *(float4*)(&Bs[br][bc]) =
                *(const float4*)(B + (size_t)(k0 + br) * ldB + col0 + bc);
        }
        __syncthreads();
#pragma unroll
        for (int kk = 0; kk < BK; kk++) {
            float af[8], bf[8];
#pragma unroll
            for (int i = 0; i < 8; i++) af[i] = As[kk][ty * 8 + i];
#pragma unroll
            for (int j = 0; j < 8; j++) bf[j] = Bs[kk][tx * 8 + j];
#pragma unroll
            for (int i = 0; i < 8; i++)
#pragma unroll
                for (int j = 0; j < 8; j++)
                    acc[i][j] = fmaf(af[i], bf[j], acc[i][j]);
        }
        __syncthreads();
    }
}

// ---------------- node-side batched GEMM (z selects weight/out/bias) --------
struct Ptr4 {
    const float* B[4];
    float* C[4];
    const float* bias[4];
};

__global__ void __launch_bounds__(256) k_node_gemm(const float* __restrict__ A,
                                                   Ptr4 p, int M)
{
    __shared__ float As[BK][AS_LD];
    __shared__ float Bs[BK][BN];
    float acc[8][8] = {};
    const int z = blockIdx.z;
    const int row0 = blockIdx.x * BM;
    const int col0 = blockIdx.y * BN;
    gemm_mainloop(A, p.B[z], M, Uu, Uu, row0, col0, As, Bs, acc);

    const float* bias = p.bias[z];
    float* C = p.C[z];
    const int tx = threadIdx.x & 15, ty = threadIdx.x >> 4;
#pragma unroll
    for (int i = 0; i < 8; i++) {
        int r = row0 + ty * 8 + i;
        if (r >= M) continue;
#pragma unroll
        for (int j4 = 0; j4 < 8; j4 += 4) {
            int c = col0 + tx * 8 + j4;
            float4 v;
            v.x = acc[i][j4 + 0];
            v.y = acc[i][j4 + 1];
            v.z = acc[i][j4 + 2];
            v.w = acc[i][j4 + 3];
            if (bias) {
                v.x += bias[c + 0];
                v.y += bias[c + 1];
                v.z += bias[c + 2];
                v.w += bias[c + 3];
            }
            *(float4*)(C + (size_t)r * Uu + c) = v;
        }
    }
}

// ---------------- fused edge update: e_new = e + relu(e@We + xWs[s]+xWt[d]+be)
__global__ void __launch_bounds__(256) k_edge_gemm(
    const float* __restrict__ Eold, const float* __restrict__ Wel,
    const float* __restrict__ bel,
    const float* __restrict__ xWs, const float* __restrict__ xWt,
    const int* __restrict__ src, const int* __restrict__ dst,
    float* __restrict__ Enew)
{
    __shared__ float As[BK][AS_LD];
    __shared__ float Bs[BK][BN];
    __shared__ int src_s[BM];
    __shared__ int dst_s[BM];
    float acc[8][8] = {};
    const int row0 = blockIdx.x * BM;
    const int col0 = blockIdx.y * BN;
    if (threadIdx.x < BM) {
        src_s[threadIdx.x] = src[row0 + threadIdx.x];
        dst_s[threadIdx.x] = dst[row0 + threadIdx.x];
    }
    // visibility guaranteed by the __syncthreads inside gemm_mainloop
    gemm_mainloop(Eold, Wel, Ee, Uu, Uu, row0, col0, As, Bs, acc);

    const int tx = threadIdx.x & 15, ty = threadIdx.x >> 4;
#pragma unroll
    for (int i = 0; i < 8; i++) {
        int r = row0 + ty * 8 + i;
        int s = src_s[ty * 8 + i];
        int d = dst_s[ty * 8 + i];
#pragma unroll
        for (int j4 = 0; j4 < 8; j4 += 4) {
            int c = col0 + tx * 8 + j4;
            float4 ws = *(const float4*)(xWs + (size_t)s * Uu + c);
            float4 wt = *(const float4*)(xWt + (size_t)d * Uu + c);
            float4 bb = *(const float4*)(bel + c);
            float4 eo = *(const float4*)(Eold + (size_t)r * Uu + c);
            float4 v;
            v.x = eo.x + fmaxf(acc[i][j4 + 0] + ws.x + wt.x + bb.x, 0.f);
            v.y = eo.y + fmaxf(acc[i][j4 + 1] + ws.y + wt.y + bb.y, 0.f);
            v.z = eo.z + fmaxf(acc[i][j4 + 2] + ws.z + wt.z + bb.z, 0.f);
            v.w = eo.w + fmaxf(acc[i][j4 + 3] + ws.w + wt.w + bb.w, 0.f);
            *(float4*)(Enew + (size_t)r * Uu + c) = v;
        }
    }
}

// ---------------- fused MLP head: out = prelu([e|a]@Wm1 + bm1) @ Wm2 + bm2 --
__global__ void __launch_bounds__(256) k_mlp(
    const float* __restrict__ Efin, const float* __restrict__ ain,
    const float* __restrict__ Wm1, const float* __restrict__ bm1,
    const float* __restrict__ alpha, const float* __restrict__ Wm2,
    const float* __restrict__ bm2, float* __restrict__ outp)
{
    __shared__ float As[BK][AS_LD];
    __shared__ float Bs[BK][BN];
    __shared__ float red[BM][17];
    float acc[8][8] = {};
    const int row0 = blockIdx.x * BM;
    gemm_mainloop(Efin, Wm1, Ee, Uu, 128, row0, 0, As, Bs, acc);

    const int tx = threadIdx.x & 15, ty = threadIdx.x >> 4;
    float wlast[8], b1r[8], w2r[8];
#pragma unroll
    for (int j = 0; j < 8; j++) {
        int c = tx * 8 + j;
        wlast[j] = Wm1[256 * 128 + c];  // row 256 of Wm1: the edge_attr column
        b1r[j] = bm1[c];
        w2r[j] = Wm2[c];
    }
    const float al = alpha[0];
#pragma unroll
    for (int i = 0; i < 8; i++) {
        int r = row0 + ty * 8 + i;
        float a = ain[r];
        float part = 0.f;
#pragma unroll
        for (int j = 0; j < 8; j++) {
            float h = acc[i][j] + a * wlast[j] + b1r[j];
            h = (h > 0.f) ? h : al * h;
            part = fmaf(h, w2r[j], part);
        }
        red[ty * 8 + i][tx] = part;
    }
    __syncthreads();
    if (threadIdx.x < BM) {
        float sum = 0.f;
#pragma unroll
        for (int t = 0; t < 16; t++) sum += red[threadIdx.x][t];
        outp[row0 + threadIdx.x] = sum + bm2[0];
    }
}

// ---------------- elementwise / scatter kernels ------------------------------
__global__ void k_init_x(const float* __restrict__ pos,
                         const float* __restrict__ Wp,
                         const float* __restrict__ bp)
{
    int t = blockIdx.x * blockDim.x + threadIdx.x;
    if (t >= Nn * Uu) return;
    int i = t >> 8, j = t & 255;
    g_x[t] = fmaf(pos[2 * i], Wp[j], fmaf(pos[2 * i + 1], Wp[Uu + j], bp[j]));
}

__global__ void k_init_e(const float* __restrict__ a,
                         const float* __restrict__ Wa,
                         const float* __restrict__ ba,
                         float* __restrict__ e)
{
    int t = blockIdx.x * blockDim.x + threadIdx.x;  // float4 granularity
    if (t >= Ee * (Uu / 4)) return;
    int i = t >> 6;
    int j = (t & 63) << 2;
    float av = a[i];
    float4 w = *(const float4*)(Wa + j);
    float4 b = *(const float4*)(ba + j);
    float4 v;
    v.x = fmaf(av, w.x, b.x);
    v.y = fmaf(av, w.y, b.y);
    v.z = fmaf(av, w.z, b.z);
    v.w = fmaf(av, w.w, b.w);
    *(float4*)(e + (size_t)i * Uu + j) = v;
}

__global__ void k_zero_agg()
{
    int t = blockIdx.x * blockDim.x + threadIdx.x;
    if (t >= Nn * Uu / 4) return;
    *(float4*)(g_agg + (size_t)t * 4) = make_float4(0.f, 0.f, 0.f, 0.f);
}

__global__ void k_msg(const float* __restrict__ e,
                      const float* __restrict__ xW2,
                      const int* __restrict__ src,
                      const int* __restrict__ dst)
{
    int t = blockIdx.x * blockDim.x + threadIdx.x;  // float4 granularity
    if (t >= Ee * (Uu / 4)) return;
    int i = t >> 6;
    int j = (t & 63) << 2;
    float4 ev = *(const float4*)(e + (size_t)i * Uu + j);
    int s = __ldg(src + i);
    int d = __ldg(dst + i);
    float4 xv = *(const float4*)(xW2 + (size_t)s * Uu + j);
    // sigmoid(e) * (x@W2 + b2)
    float4 m;
    m.x = xv.x / (1.f + __expf(-ev.x));
    m.y = xv.y / (1.f + __expf(-ev.y));
    m.z = xv.z / (1.f + __expf(-ev.z));
    m.w = xv.w / (1.f + __expf(-ev.w));
    float* ap = g_agg + (size_t)d * Uu + j;
    atomicAdd(ap + 0, m.x);
    atomicAdd(ap + 1, m.y);
    atomicAdd(ap + 2, m.z);
    atomicAdd(ap + 3, m.w);
}

__global__ void k_node_update()
{
    int t = blockIdx.x * blockDim.x + threadIdx.x;
    if (t >= Nn * Uu) return;
    g_x[t] += fmaxf(g_xW1[t] + g_agg[t], 0.f);
}

// ---------------- host driver ------------------------------------------------
extern "C" void kernel_launch(void* const* d_in, const int* in_sizes, int n_in,
                              void* d_out, int out_size)
{
    const float* pos   = (const float*)d_in[0];
    const float* ain   = (const float*)d_in[1];
    const int*   eidx  = (const int*)d_in[2];
    const float* Wp    = (const float*)d_in[3];
    const float* bp    = (const float*)d_in[4];
    const float* Wa    = (const float*)d_in[5];
    const float* ba    = (const float*)d_in[6];
    const float* W1    = (const float*)d_in[7];
    const float* b1    = (const float*)d_in[8];
    const float* W2    = (const float*)d_in[9];
    const float* b2    = (const float*)d_in[10];
    const float* We    = (const float*)d_in[11];
    const float* be    = (const float*)d_in[12];
    const float* Ws    = (const float*)d_in[13];
    const float* Wt    = (const float*)d_in[14];
    const float* Wm1   = (const float*)d_in[15];
    const float* bm1   = (const float*)d_in[16];
    const float* alpha = (const float*)d_in[17];
    const float* Wm2   = (const float*)d_in[18];
    const float* bm2   = (const float*)d_in[19];
    float* outp = (float*)d_out;

    const int* src = eidx;        // edge_index[0]
    const int* dst = eidx + Ee;   // edge_index[1]

    float *px, *pxW1, *pxW2, *pxWs, *pxWt, *pe0, *pe1;
    cudaGetSymbolAddress((void**)&px,   g_x);
    cudaGetSymbolAddress((void**)&pxW1, g_xW1);
    cudaGetSymbolAddress((void**)&pxW2, g_xW2);
    cudaGetSymbolAddress((void**)&pxWs, g_xWs);
    cudaGetSymbolAddress((void**)&pxWt, g_xWt);
    cudaGetSymbolAddress((void**)&pe0,  g_e0);
    cudaGetSymbolAddress((void**)&pe1,  g_e1);

    const int nodeRowBlocks = (Nn + BM - 1) / BM;  // 79
    const int ew_grid = (Ee * (Uu / 4) + 255) / 256;

    k_init_x<<<(Nn * Uu + 255) / 256, 256>>>(pos, Wp, bp);
    k_init_e<<<ew_grid, 256>>>(ain, Wa, ba, pe0);

    float* ecur = pe0;
    float* enxt = pe1;

    for (int l = 0; l < Ll; l++) {
        Ptr4 p;
        p.B[0] = W1 + (size_t)l * Uu * Uu;
        p.B[1] = W2 + (size_t)l * Uu * Uu;
        p.B[2] = Ws + (size_t)l * Uu * Uu;
        p.B[3] = Wt + (size_t)l * Uu * Uu;
        p.C[0] = pxW1; p.C[1] = pxW2; p.C[2] = pxWs; p.C[3] = pxWt;
        p.bias[0] = b1 + (size_t)l * Uu;
        p.bias[1] = b2 + (size_t)l * Uu;
        p.bias[2] = nullptr;
        p.bias[3] = nullptr;
        k_node_gemm<<<dim3(nodeRowBlocks, 2, 4), 256>>>(px, p, Nn);

        k_zero_agg<<<(Nn * Uu / 4 + 255) / 256, 256>>>();
        k_msg<<<ew_grid, 256>>>(ecur, pxW2, src, dst);

        k_edge_gemm<<<dim3(Ee / BM, 2), 256>>>(ecur, We + (size_t)l * Uu * Uu,
                                               be + (size_t)l * Uu,
                                               pxWs, pxWt, src, dst, enxt);

        k_node_update<<<(Nn * Uu + 255) / 256, 256>>>();

        float* tmp = ecur; ecur = enxt; enxt = tmp;
    }

    // final edge update (l = L)
    {
        Ptr4 p;
        p.B[0] = Ws + (size_t)Ll * Uu * Uu;
        p.B[1] = Wt + (size_t)Ll * Uu * Uu;
        p.B[2] = p.B[0]; p.B[3] = p.B[0];
        p.C[0] = pxWs; p.C[1] = pxWt; p.C[2] = pxWs; p.C[3] = pxWs;
        p.bias[0] = nullptr; p.bias[1] = nullptr;
        p.bias[2] = nullptr; p.bias[3] = nullptr;
        k_node_gemm<<<dim3(nodeRowBlocks, 2, 2), 256>>>(px, p, Nn);

        k_edge_gemm<<<dim3(Ee / BM, 2), 256>>>(ecur, We + (size_t)Ll * Uu * Uu,
                                               be + (size_t)Ll * Uu,
                                               pxWs, pxWt, src, dst, enxt);
        float* tmp = ecur; ecur = enxt; enxt = tmp;
    }

    k_mlp<<<Ee / BM, 256>>>(ecur, ain, Wm1, bm1, alpha, Wm2, bm2, outp);
}

// round 9
// speedup vs baseline: 1.1978x; 1.1978x over previous
#include <cuda_runtime.h>
#include <cuda_bf16.h>
#include <cstdint>
#include <cstddef>

#define Nn 10000
#define Ee 320000
#define Uu 256
#define Ll 3

#define BM 128
#define BN 128
#define BK 16
#define AS_LD 136

// ---------------- scratch (device globals; no allocations allowed) ----------
__device__ float g_x[Nn * Uu];
__device__ float g_xW1[Nn * Uu];
__device__ float g_xW2[Nn * Uu];
__device__ float g_xWs[Nn * Uu];
__device__ float g_xWt[Nn * Uu];
__device__ float g_agg[Nn * Uu];
__device__ float g_e0[(size_t)Ee * Uu];
__device__ float g_e1[(size_t)Ee * Uu];
// pre-split edge weights, [l][n][k] K-major bf16 (hi & lo parts)
__device__ __nv_bfloat16 g_WeH[(Ll + 1) * Uu * Uu];
__device__ __nv_bfloat16 g_WeL[(Ll + 1) * Uu * Uu];

// ---------------- helpers ----------------------------------------------------
__device__ __forceinline__ void split2(float a, float b, uint32_t& h, uint32_t& l)
{
    __nv_bfloat16 ha = __float2bfloat16(a);
    __nv_bfloat16 hb = __float2bfloat16(b);
    __nv_bfloat162 hp;
    hp.x = ha; hp.y = hb;
    h = *reinterpret_cast<uint32_t*>(&hp);
    __nv_bfloat162 lp;
    lp.x = __float2bfloat16(a - __bfloat162float(ha));
    lp.y = __float2bfloat16(b - __bfloat162float(hb));
    l = *reinterpret_cast<uint32_t*>(&lp);
}

__device__ __forceinline__ void mma16816(float* c, const uint32_t* a,
                                         const uint32_t* b)
{
    asm volatile(
        "mma.sync.aligned.m16n8k16.row.col.f32.bf16.bf16.f32 "
        "{%0,%1,%2,%3}, {%4,%5,%6,%7}, {%8,%9}, {%0,%1,%2,%3};"
        : "+f"(c[0]), "+f"(c[1]), "+f"(c[2]), "+f"(c[3])
        : "r"(a[0]), "r"(a[1]), "r"(a[2]), "r"(a[3]), "r"(b[0]), "r"(b[1]));
}

// SMEM row stride for bf16 tiles: 40 elements (80 B) => fragment-load bank map
// (20*g + t) % 32 is all-distinct across a warp -> conflict-free LDS.32.
#define SLD 40

// ---- tensor-core (HMMA) fused edge update:
//      Enew = Eold + relu(Eold@We + xWs[src] + xWt[dst] + be)
// CTA: 256 thr (8 warps), tile M=128 x N=128, K chunked by 32, split-3 bf16.
__global__ void __launch_bounds__(256) k_edge_mma(
    const float* __restrict__ Eold,
    const __nv_bfloat16* __restrict__ Wh,  // [N=256][K=256] K-major (pre-split hi)
    const __nv_bfloat16* __restrict__ Wl,  //                              (lo)
    const float* __restrict__ bel,
    const float* __restrict__ xWs, const float* __restrict__ xWt,
    const int* __restrict__ src, const int* __restrict__ dst,
    float* __restrict__ Enew)
{
    __shared__ __nv_bfloat16 sAh[128][SLD];
    __shared__ __nv_bfloat16 sAl[128][SLD];
    __shared__ __nv_bfloat16 sBh[128][SLD];
    __shared__ __nv_bfloat16 sBl[128][SLD];
    __shared__ int src_s[BM];
    __shared__ int dst_s[BM];

    const int tid = threadIdx.x;
    const int wid = tid >> 5;
    const int lane = tid & 31;
    const int g = lane >> 2;     // group row 0..7
    const int tg = lane & 3;     // thread-in-group 0..3
    const int row0 = blockIdx.x * BM;
    const int col0 = blockIdx.y * BN;
    const int m0 = (wid & 3) * 32;   // warp M offset within tile
    const int n0 = (wid >> 2) * 64;  // warp N offset within tile

    if (tid < BM) {
        src_s[tid] = src[row0 + tid];
        dst_s[tid] = dst[row0 + tid];
    }

    // fill assignments: each thread owns (row, 16-wide k-half) per chunk
    const int frow = tid >> 1;
    const int fkh = (tid & 1) * 16;
    const float4* arow = (const float4*)(Eold + (size_t)(row0 + frow) * Uu);
    const uint4* bhrow = (const uint4*)(Wh + (size_t)(col0 + frow) * Uu);
    const uint4* blrow = (const uint4*)(Wl + (size_t)(col0 + frow) * Uu);

    float acc[2][8][4];
#pragma unroll
    for (int mt = 0; mt < 2; mt++)
#pragma unroll
        for (int nt = 0; nt < 8; nt++)
#pragma unroll
            for (int q = 0; q < 4; q++) acc[mt][nt][q] = 0.f;

    for (int kc = 0; kc < 8; kc++) {  // K = 8 chunks of 32
        __syncthreads();
        // ---- fill A (fp32 -> bf16 hi/lo) ----
#pragma unroll
        for (int q = 0; q < 4; q++) {
            float4 f = arow[((kc * 32 + fkh) >> 2) + q];
            uint32_t h0, l0, h1, l1;
            split2(f.x, f.y, h0, l0);
            split2(f.z, f.w, h1, l1);
            *(uint32_t*)&sAh[frow][fkh + 4 * q]     = h0;
            *(uint32_t*)&sAh[frow][fkh + 4 * q + 2] = h1;
            *(uint32_t*)&sAl[frow][fkh + 4 * q]     = l0;
            *(uint32_t*)&sAl[frow][fkh + 4 * q + 2] = l1;
        }
        // ---- fill B (pre-split bf16, 16B-aligned uint4 stores) ----
        {
            int bi = (kc * 32 + fkh) >> 3;
            *(uint4*)&sBh[frow][fkh]     = bhrow[bi];
            *(uint4*)&sBh[frow][fkh + 8] = bhrow[bi + 1];
            *(uint4*)&sBl[frow][fkh]     = blrow[bi];
            *(uint4*)&sBl[frow][fkh + 8] = blrow[bi + 1];
        }
        __syncthreads();

        // ---- 3 passes: Ah*Bh, Ah*Bl, Al*Bh ----
#pragma unroll
        for (int pass = 0; pass < 3; pass++) {
            const __nv_bfloat16 (*Ap)[SLD] = (pass == 2) ? sAl : sAh;
            const __nv_bfloat16 (*Bp)[SLD] = (pass == 1) ? sBl : sBh;
#pragma unroll
            for (int ks = 0; ks < 2; ks++) {
                const int kb = ks * 16 + tg * 2;
                uint32_t a[2][4], b[8][2];
#pragma unroll
                for (int mt = 0; mt < 2; mt++) {
                    int mr = m0 + mt * 16 + g;
                    a[mt][0] = *(const uint32_t*)&Ap[mr][kb];
                    a[mt][1] = *(const uint32_t*)&Ap[mr + 8][kb];
                    a[mt][2] = *(const uint32_t*)&Ap[mr][kb + 8];
                    a[mt][3] = *(const uint32_t*)&Ap[mr + 8][kb + 8];
                }
#pragma unroll
                for (int nt = 0; nt < 8; nt++) {
                    int nr = n0 + nt * 8 + g;
                    b[nt][0] = *(const uint32_t*)&Bp[nr][kb];
                    b[nt][1] = *(const uint32_t*)&Bp[nr][kb + 8];
                }
#pragma unroll
                for (int mt = 0; mt < 2; mt++)
#pragma unroll
                    for (int nt = 0; nt < 8; nt++)
                        mma16816(acc[mt][nt], a[mt], b[nt]);
            }
        }
    }

    // ---- fused epilogue -----------------------------------------------------
#pragma unroll
    for (int mt = 0; mt < 2; mt++) {
#pragma unroll
        for (int h = 0; h < 2; h++) {
            int lrow = m0 + mt * 16 + g + h * 8;
            int r = row0 + lrow;
            int s = src_s[lrow];
            int d = dst_s[lrow];
            const float* wsp = xWs + (size_t)s * Uu + col0 + n0;
            const float* wtp = xWt + (size_t)d * Uu + col0 + n0;
            const float* eop = Eold + (size_t)r * Uu + col0 + n0;
            const float* bbp = bel + col0 + n0;
            float* outp = Enew + (size_t)r * Uu + col0 + n0;
#pragma unroll
            for (int nt = 0; nt < 8; nt++) {
                int c = nt * 8 + tg * 2;
                float2 ws = *(const float2*)(wsp + c);
                float2 wt = *(const float2*)(wtp + c);
                float2 eo = *(const float2*)(eop + c);
                float2 bb = *(const float2*)(bbp + c);
                float a0 = acc[mt][nt][h * 2 + 0];
                float a1 = acc[mt][nt][h * 2 + 1];
                float2 v;
                v.x = eo.x + fmaxf(a0 + ws.x + wt.x + bb.x, 0.f);
                v.y = eo.y + fmaxf(a1 + ws.y + wt.y + bb.y, 0.f);
                *(float2*)(outp + c) = v;
            }
        }
    }
}

// ---- weight pre-split: WeH/WeL[l][n][k] = bf16 hi/lo of We[l][k][n] ---------
__global__ void k_prep_we(const float* __restrict__ We)
{
    int t = blockIdx.x * blockDim.x + threadIdx.x;
    if (t >= (Ll + 1) * Uu * Uu) return;
    int l = t >> 16;
    int n = (t >> 8) & 255;
    int k = t & 255;
    float w = We[(size_t)l * Uu * Uu + k * Uu + n];
    __nv_bfloat16 h = __float2bfloat16(w);
    g_WeH[t] = h;
    g_WeL[t] = __float2bfloat16(w - __bfloat162float(h));
}

// ======================= fp32 SGEMM path (node/mlp) =========================
__device__ __forceinline__ void gemm_mainloop(
    const float* __restrict__ A, const float* __restrict__ B,
    int M, int K, int ldB, int row0, int col0,
    float (*As)[AS_LD], float (*Bs)[BN], float acc[8][8])
{
    const int tid = threadIdx.x;
    const int tx = tid & 15, ty = tid >> 4;
    for (int k0 = 0; k0 < K; k0 += BK) {
#pragma unroll
        for (int v = 0; v < 2; v++) {
            int idx = tid + v * 256;
            int ar = idx >> 2;
            int ak = (idx & 3) << 2;
            int grow = row0 + ar;
            float4 av = make_float4(0.f, 0.f, 0.f, 0.f);
            if (grow < M)
                av = *(const float4*)(A + (size_t)grow * K + k0 + ak);
            As[ak + 0][ar] = av.x;
            As[ak + 1][ar] = av.y;
            As[ak + 2][ar] = av.z;
            As[ak + 3][ar] = av.w;
            int br = idx >> 5;
            int bc = (idx & 31) << 2;
            *(float4*)(&Bs[br][bc]) =
                *(const float4*)(B + (size_t)(k0 + br) * ldB + col0 + bc);
        }
        __syncthreads();
#pragma unroll
        for (int kk = 0; kk < BK; kk++) {
            float af[8], bf[8];
#pragma unroll
            for (int i = 0; i < 8; i++) af[i] = As[kk][ty * 8 + i];
#pragma unroll
            for (int j = 0; j < 8; j++) bf[j] = Bs[kk][tx * 8 + j];
#pragma unroll
            for (int i = 0; i < 8; i++)
#pragma unroll
                for (int j = 0; j < 8; j++)
                    acc[i][j] = fmaf(af[i], bf[j], acc[i][j]);
        }
        __syncthreads();
    }
}

struct Ptr4 {
    const float* B[4];
    float* C[4];
    const float* bias[4];
};

__global__ void __launch_bounds__(256) k_node_gemm(const float* __restrict__ A,
                                                   Ptr4 p, int M)
{
    __shared__ float As[BK][AS_LD];
    __shared__ float Bs[BK][BN];
    float acc[8][8] = {};
    const int z = blockIdx.z;
    const int row0 = blockIdx.x * BM;
    const int col0 = blockIdx.y * BN;
    gemm_mainloop(A, p.B[z], M, Uu, Uu, row0, col0, As, Bs, acc);

    const float* bias = p.bias[z];
    float* C = p.C[z];
    const int tx = threadIdx.x & 15, ty = threadIdx.x >> 4;
#pragma unroll
    for (int i = 0; i < 8; i++) {
        int r = row0 + ty * 8 + i;
        if (r >= M) continue;
#pragma unroll
        for (int j4 = 0; j4 < 8; j4 += 4) {
            int c = col0 + tx * 8 + j4;
            float4 v;
            v.x = acc[i][j4 + 0];
            v.y = acc[i][j4 + 1];
            v.z = acc[i][j4 + 2];
            v.w = acc[i][j4 + 3];
            if (bias) {
                v.x += bias[c + 0];
                v.y += bias[c + 1];
                v.z += bias[c + 2];
                v.w += bias[c + 3];
            }
            *(float4*)(C + (size_t)r * Uu + c) = v;
        }
    }
}

__global__ void __launch_bounds__(256) k_mlp(
    const float* __restrict__ Efin, const float* __restrict__ ain,
    const float* __restrict__ Wm1, const float* __restrict__ bm1,
    const float* __restrict__ alpha, const float* __restrict__ Wm2,
    const float* __restrict__ bm2, float* __restrict__ outp)
{
    __shared__ float As[BK][AS_LD];
    __shared__ float Bs[BK][BN];
    __shared__ float red[BM][17];
    float acc[8][8] = {};
    const int row0 = blockIdx.x * BM;
    gemm_mainloop(Efin, Wm1, Ee, Uu, 128, row0, 0, As, Bs, acc);

    const int tx = threadIdx.x & 15, ty = threadIdx.x >> 4;
    float wlast[8], b1r[8], w2r[8];
#pragma unroll
    for (int j = 0; j < 8; j++) {
        int c = tx * 8 + j;
        wlast[j] = Wm1[256 * 128 + c];
        b1r[j] = bm1[c];
        w2r[j] = Wm2[c];
    }
    const float al = alpha[0];
#pragma unroll
    for (int i = 0; i < 8; i++) {
        int r = row0 + ty * 8 + i;
        float a = ain[r];
        float part = 0.f;
#pragma unroll
        for (int j = 0; j < 8; j++) {
            float h = acc[i][j] + a * wlast[j] + b1r[j];
            h = (h > 0.f) ? h : al * h;
            part = fmaf(h, w2r[j], part);
        }
        red[ty * 8 + i][tx] = part;
    }
    __syncthreads();
    if (threadIdx.x < BM) {
        float sum = 0.f;
#pragma unroll
        for (int t = 0; t < 16; t++) sum += red[threadIdx.x][t];
        outp[row0 + threadIdx.x] = sum + bm2[0];
    }
}

// ---------------- elementwise / scatter kernels ------------------------------
__global__ void k_init_x(const float* __restrict__ pos,
                         const float* __restrict__ Wp,
                         const float* __restrict__ bp)
{
    int t = blockIdx.x * blockDim.x + threadIdx.x;
    if (t >= Nn * Uu) return;
    int i = t >> 8, j = t & 255;
    g_x[t] = fmaf(pos[2 * i], Wp[j], fmaf(pos[2 * i + 1], Wp[Uu + j], bp[j]));
}

__global__ void k_init_e(const float* __restrict__ a,
                         const float* __restrict__ Wa,
                         const float* __restrict__ ba,
                         float* __restrict__ e)
{
    int t = blockIdx.x * blockDim.x + threadIdx.x;
    if (t >= Ee * (Uu / 4)) return;
    int i = t >> 6;
    int j = (t & 63) << 2;
    float av = a[i];
    float4 w = *(const float4*)(Wa + j);
    float4 b = *(const float4*)(ba + j);
    float4 v;
    v.x = fmaf(av, w.x, b.x);
    v.y = fmaf(av, w.y, b.y);
    v.z = fmaf(av, w.z, b.z);
    v.w = fmaf(av, w.w, b.w);
    *(float4*)(e + (size_t)i * Uu + j) = v;
}

__global__ void k_zero_agg()
{
    int t = blockIdx.x * blockDim.x + threadIdx.x;
    if (t >= Nn * Uu / 4) return;
    *(float4*)(g_agg + (size_t)t * 4) = make_float4(0.f, 0.f, 0.f, 0.f);
}

__global__ void k_msg(const float* __restrict__ e,
                      const float* __restrict__ xW2,
                      const int* __restrict__ src,
                      const int* __restrict__ dst)
{
    int t = blockIdx.x * blockDim.x + threadIdx.x;
    if (t >= Ee * (Uu / 4)) return;
    int i = t >> 6;
    int j = (t & 63) << 2;
    float4 ev = *(const float4*)(e + (size_t)i * Uu + j);
    int s = __ldg(src + i);
    int d = __ldg(dst + i);
    float4 xv = *(const float4*)(xW2 + (size_t)s * Uu + j);
    float4 m;
    m.x = xv.x / (1.f + __expf(-ev.x));
    m.y = xv.y / (1.f + __expf(-ev.y));
    m.z = xv.z / (1.f + __expf(-ev.z));
    m.w = xv.w / (1.f + __expf(-ev.w));
    float* ap = g_agg + (size_t)d * Uu + j;
    atomicAdd(ap + 0, m.x);
    atomicAdd(ap + 1, m.y);
    atomicAdd(ap + 2, m.z);
    atomicAdd(ap + 3, m.w);
}

__global__ void k_node_update()
{
    int t = blockIdx.x * blockDim.x + threadIdx.x;
    if (t >= Nn * Uu) return;
    g_x[t] += fmaxf(g_xW1[t] + g_agg[t], 0.f);
}

// ---------------- host driver ------------------------------------------------
extern "C" void kernel_launch(void* const* d_in, const int* in_sizes, int n_in,
                              void* d_out, int out_size)
{
    const float* pos   = (const float*)d_in[0];
    const float* ain   = (const float*)d_in[1];
    const int*   eidx  = (const int*)d_in[2];
    const float* Wp    = (const float*)d_in[3];
    const float* bp    = (const float*)d_in[4];
    const float* Wa    = (const float*)d_in[5];
    const float* ba    = (const float*)d_in[6];
    const float* W1    = (const float*)d_in[7];
    const float* b1    = (const float*)d_in[8];
    const float* W2    = (const float*)d_in[9];
    const float* b2    = (const float*)d_in[10];
    const float* We    = (const float*)d_in[11];
    const float* be    = (const float*)d_in[12];
    const float* Ws    = (const float*)d_in[13];
    const float* Wt    = (const float*)d_in[14];
    const float* Wm1   = (const float*)d_in[15];
    const float* bm1   = (const float*)d_in[16];
    const float* alpha = (const float*)d_in[17];
    const float* Wm2   = (const float*)d_in[18];
    const float* bm2   = (const float*)d_in[19];
    float* outp = (float*)d_out;

    const int* src = eidx;
    const int* dst = eidx + Ee;

    float *px, *pxW1, *pxW2, *pxWs, *pxWt, *pe0, *pe1;
    __nv_bfloat16 *pWH, *pWL;
    cudaGetSymbolAddress((void**)&px,   g_x);
    cudaGetSymbolAddress((void**)&pxW1, g_xW1);
    cudaGetSymbolAddress((void**)&pxW2, g_xW2);
    cudaGetSymbolAddress((void**)&pxWs, g_xWs);
    cudaGetSymbolAddress((void**)&pxWt, g_xWt);
    cudaGetSymbolAddress((void**)&pe0,  g_e0);
    cudaGetSymbolAddress((void**)&pe1,  g_e1);
    cudaGetSymbolAddress((void**)&pWH,  g_WeH);
    cudaGetSymbolAddress((void**)&pWL,  g_WeL);

    const int nodeRowBlocks = (Nn + BM - 1) / BM;
    const int ew_grid = (Ee * (Uu / 4) + 255) / 256;

    k_init_x<<<(Nn * Uu + 255) / 256, 256>>>(pos, Wp, bp);
    k_init_e<<<ew_grid, 256>>>(ain, Wa, ba, pe0);
    k_prep_we<<<((Ll + 1) * Uu * Uu + 255) / 256, 256>>>(We);

    float* ecur = pe0;
    float* enxt = pe1;

    for (int l = 0; l < Ll; l++) {
        Ptr4 p;
        p.B[0] = W1 + (size_t)l * Uu * Uu;
        p.B[1] = W2 + (size_t)l * Uu * Uu;
        p.B[2] = Ws + (size_t)l * Uu * Uu;
        p.B[3] = Wt + (size_t)l * Uu * Uu;
        p.C[0] = pxW1; p.C[1] = pxW2; p.C[2] = pxWs; p.C[3] = pxWt;
        p.bias[0] = b1 + (size_t)l * Uu;
        p.bias[1] = b2 + (size_t)l * Uu;
        p.bias[2] = nullptr;
        p.bias[3] = nullptr;
        k_node_gemm<<<dim3(nodeRowBlocks, 2, 4), 256>>>(px, p, Nn);

        k_zero_agg<<<(Nn * Uu / 4 + 255) / 256, 256>>>();
        k_msg<<<ew_grid, 256>>>(ecur, pxW2, src, dst);

        k_edge_mma<<<dim3(Ee / BM, 2), 256>>>(
            ecur, pWH + (size_t)l * Uu * Uu, pWL + (size_t)l * Uu * Uu,
            be + (size_t)l * Uu, pxWs, pxWt, src, dst, enxt);

        k_node_update<<<(Nn * Uu + 255) / 256, 256>>>();

        float* tmp = ecur; ecur = enxt; enxt = tmp;
    }

    // final edge update (l = L)
    {
        Ptr4 p;
        p.B[0] = Ws + (size_t)Ll * Uu * Uu;
        p.B[1] = Wt + (size_t)Ll * Uu * Uu;
        p.B[2] = p.B[0]; p.B[3] = p.B[0];
        p.C[0] = pxWs; p.C[1] = pxWt; p.C[2] = pxWs; p.C[3] = pxWs;
        p.bias[0] = nullptr; p.bias[1] = nullptr;
        p.bias[2] = nullptr; p.bias[3] = nullptr;
        k_node_gemm<<<dim3(nodeRowBlocks, 2, 2), 256>>>(px, p, Nn);

        k_edge_mma<<<dim3(Ee / BM, 2), 256>>>(
            ecur, pWH + (size_t)Ll * Uu * Uu, pWL + (size_t)Ll * Uu * Uu,
            be + (size_t)Ll * Uu, pxWs, pxWt, src, dst, enxt);
        float* tmp = ecur; ecur = enxt; enxt = tmp;
    }

    k_mlp<<<Ee / BM, 256>>>(ecur, ain, Wm1, bm1, alpha, Wm2, bm2, outp);
}

// round 12
// speedup vs baseline: 1.4074x; 1.1750x over previous
#include <cuda_runtime.h>
#include <cuda_bf16.h>
#include <cstdint>
#include <cstddef>

#define Nn 10000
#define Ee 320000
#define Uu 256
#define Ll 3

#define BM 128
#define BN 128
#define BK 16
#define AS_LD 136

// ---------------- scratch (device globals; no allocations allowed) ----------
__device__ float g_x[Nn * Uu];
__device__ float g_xW1[Nn * Uu];
__device__ float g_xW2[Nn * Uu];
__device__ float g_xWs[Nn * Uu];
__device__ float g_xWt[Nn * Uu];
__device__ float g_agg[Nn * Uu];
__device__ float g_e0[(size_t)Ee * Uu];
__device__ float g_e1[(size_t)Ee * Uu];
// pre-split edge weights, [l][n][k] K-major bf16 (hi & lo parts)
__device__ __nv_bfloat16 g_WeH[(Ll + 1) * Uu * Uu];
__device__ __nv_bfloat16 g_WeL[(Ll + 1) * Uu * Uu];
// pre-split MLP weight Wm1[0:256,:] -> [n=128][k=256] K-major hi/lo
__device__ __nv_bfloat16 g_Wm1H[128 * Uu];
__device__ __nv_bfloat16 g_Wm1L[128 * Uu];

// ---------------- helpers ----------------------------------------------------
__device__ __forceinline__ uint32_t smem_u32(const void* p) {
    uint32_t a;
    asm("{ .reg .u64 t; cvta.to.shared.u64 t, %1; cvt.u32.u64 %0, t; }"
        : "=r"(a) : "l"(p));
    return a;
}

__device__ __forceinline__ void cp16(uint32_t s, const void* g) {
    asm volatile("cp.async.cg.shared.global [%0], [%1], 16;" :: "r"(s), "l"(g));
}
#define CP_COMMIT() asm volatile("cp.async.commit_group;" ::: "memory")
#define CP_WAIT0()  asm volatile("cp.async.wait_group 0;" ::: "memory")

__device__ __forceinline__ void split2(float a, float b, uint32_t& h, uint32_t& l)
{
    __nv_bfloat16 ha = __float2bfloat16(a);
    __nv_bfloat16 hb = __float2bfloat16(b);
    __nv_bfloat162 hp;
    hp.x = ha; hp.y = hb;
    h = *reinterpret_cast<uint32_t*>(&hp);
    __nv_bfloat162 lp;
    lp.x = __float2bfloat16(a - __bfloat162float(ha));
    lp.y = __float2bfloat16(b - __bfloat162float(hb));
    l = *reinterpret_cast<uint32_t*>(&lp);
}

__device__ __forceinline__ void mma16816(float* c, const uint32_t* a,
                                         const uint32_t* b)
{
    asm volatile(
        "mma.sync.aligned.m16n8k16.row.col.f32.bf16.bf16.f32 "
        "{%0,%1,%2,%3}, {%4,%5,%6,%7}, {%8,%9}, {%0,%1,%2,%3};"
        : "+f"(c[0]), "+f"(c[1]), "+f"(c[2]), "+f"(c[3])
        : "r"(a[0]), "r"(a[1]), "r"(a[2]), "r"(a[3]), "r"(b[0]), "r"(b[1]));
}

// SMEM row stride 40 bf16 (80 B): conflict-free frag LDS (proven in R9).
#define SLD 40
#define TILE_B 10240            // 128 * 40 * 2 bytes
#define BUF_B  (4 * TILE_B)     // Ah, Al, Bh, Bl per buffer
#define SMEMB  (2 * BUF_B + 1024)

// ---- double-buffered 3-pass mainloop:
//      acc += Ah@Bh^T + Ah@Bl^T + Al@Bh^T   (fp32-accurate to ~1e-7 rel)
// A fp32 row-major ld=256; Bh/Bl bf16 K-major ld=256 (rows = output cols).
__device__ __forceinline__ void mma_mainloop_db(
    const float* __restrict__ A,
    const __nv_bfloat16* __restrict__ Bh, const __nv_bfloat16* __restrict__ Bl,
    int row0, int col0, unsigned char* sm, uint32_t smb, float acc[2][8][4])
{
    const int tid = threadIdx.x;
    const int wid = tid >> 5;
    const int lane = tid & 31;
    const int g = lane >> 2;
    const int tg = lane & 3;
    const int m0 = (wid & 3) * 32;
    const int n0 = (wid >> 2) * 64;
    const int frow = tid >> 1;
    const int fkh = (tid & 1) * 16;

    const float4* arow = (const float4*)(A + (size_t)(row0 + frow) * Uu);
    const __nv_bfloat16* bhrow = Bh + (size_t)(col0 + frow) * Uu;
    const __nv_bfloat16* blrow = Bl + (size_t)(col0 + frow) * Uu;

    const uint32_t sdst = smb + frow * 80 + fkh * 2;  // within-tile offset
    const uint32_t arow_off = frow * 80 + fkh * 2;

    float4 aPF[4];
    // ---- prologue: chunk 0 into buffer 0 ----
#pragma unroll
    for (int q = 0; q < 4; q++) aPF[q] = arow[(fkh >> 2) + q];
    {
        uint32_t db = sdst + 2 * TILE_B;  // Bh slot
        cp16(db,      bhrow + fkh);
        cp16(db + 16, bhrow + fkh + 8);
        uint32_t dl = db + TILE_B;        // Bl slot
        cp16(dl,      blrow + fkh);
        cp16(dl + 16, blrow + fkh + 8);
        CP_COMMIT();
    }
#pragma unroll
    for (int q = 0; q < 4; q++) {
        uint32_t h0, l0, h1, l1;
        split2(aPF[q].x, aPF[q].y, h0, l0);
        split2(aPF[q].z, aPF[q].w, h1, l1);
        *(uint32_t*)(sm + arow_off + (4 * q) * 2)              = h0;
        *(uint32_t*)(sm + arow_off + (4 * q + 2) * 2)          = h1;
        *(uint32_t*)(sm + TILE_B + arow_off + (4 * q) * 2)     = l0;
        *(uint32_t*)(sm + TILE_B + arow_off + (4 * q + 2) * 2) = l1;
    }
    CP_WAIT0();
    __syncthreads();

    for (int kc = 0; kc < 8; kc++) {
        const int cur = kc & 1;
        if (kc < 7) {
            const int nk = (kc + 1) * 32;
#pragma unroll
            for (int q = 0; q < 4; q++) aPF[q] = arow[((nk + fkh) >> 2) + q];
            uint32_t db = sdst + (cur ^ 1) * BUF_B + 2 * TILE_B;
            cp16(db,      bhrow + nk + fkh);
            cp16(db + 16, bhrow + nk + fkh + 8);
            uint32_t dl = db + TILE_B;
            cp16(dl,      blrow + nk + fkh);
            cp16(dl + 16, blrow + nk + fkh + 8);
            CP_COMMIT();
        }

        const __nv_bfloat16 (*ApH)[SLD] =
            (const __nv_bfloat16 (*)[SLD])(sm + cur * BUF_B);
        const __nv_bfloat16 (*ApL)[SLD] =
            (const __nv_bfloat16 (*)[SLD])(sm + cur * BUF_B + TILE_B);
        const __nv_bfloat16 (*BpH)[SLD] =
            (const __nv_bfloat16 (*)[SLD])(sm + cur * BUF_B + 2 * TILE_B);
        const __nv_bfloat16 (*BpL)[SLD] =
            (const __nv_bfloat16 (*)[SLD])(sm + cur * BUF_B + 3 * TILE_B);

        // 3 passes: (Ah,Bh), (Ah,Bl), (Al,Bh)
#pragma unroll
        for (int pass = 0; pass < 3; pass++) {
            const __nv_bfloat16 (*Ap)[SLD] = (pass == 2) ? ApL : ApH;
            const __nv_bfloat16 (*Bp)[SLD] = (pass == 1) ? BpL : BpH;
#pragma unroll
            for (int ks = 0; ks < 2; ks++) {
                const int kb = ks * 16 + tg * 2;
                uint32_t a[2][4], b[8][2];
#pragma unroll
                for (int mt = 0; mt < 2; mt++) {
                    int mr = m0 + mt * 16 + g;
                    a[mt][0] = *(const uint32_t*)&Ap[mr][kb];
                    a[mt][1] = *(const uint32_t*)&Ap[mr + 8][kb];
                    a[mt][2] = *(const uint32_t*)&Ap[mr][kb + 8];
                    a[mt][3] = *(const uint32_t*)&Ap[mr + 8][kb + 8];
                }
#pragma unroll
                for (int nt = 0; nt < 8; nt++) {
                    int nr = n0 + nt * 8 + g;
                    b[nt][0] = *(const uint32_t*)&Bp[nr][kb];
                    b[nt][1] = *(const uint32_t*)&Bp[nr][kb + 8];
                }
#pragma unroll
                for (int mt = 0; mt < 2; mt++)
#pragma unroll
                    for (int nt = 0; nt < 8; nt++)
                        mma16816(acc[mt][nt], a[mt], b[nt]);
            }
        }

        if (kc < 7) {
            unsigned char* an = sm + (cur ^ 1) * BUF_B;
#pragma unroll
            for (int q = 0; q < 4; q++) {
                uint32_t h0, l0, h1, l1;
                split2(aPF[q].x, aPF[q].y, h0, l0);
                split2(aPF[q].z, aPF[q].w, h1, l1);
                *(uint32_t*)(an + arow_off + (4 * q) * 2)              = h0;
                *(uint32_t*)(an + arow_off + (4 * q + 2) * 2)          = h1;
                *(uint32_t*)(an + TILE_B + arow_off + (4 * q) * 2)     = l0;
                *(uint32_t*)(an + TILE_B + arow_off + (4 * q + 2) * 2) = l1;
            }
            CP_WAIT0();
        }
        __syncthreads();
    }
}

// ---- tensor-core fused edge update:
//      Enew = Eold + relu(Eold@We + xWs[src] + xWt[dst] + be)
__global__ void __launch_bounds__(256) k_edge_mma(
    const float* __restrict__ Eold,
    const __nv_bfloat16* __restrict__ Wh, const __nv_bfloat16* __restrict__ Wl,
    const float* __restrict__ bel,
    const float* __restrict__ xWs, const float* __restrict__ xWt,
    const int* __restrict__ src, const int* __restrict__ dst,
    float* __restrict__ Enew)
{
    extern __shared__ __align__(16) unsigned char sm[];
    const uint32_t smb = smem_u32(sm);
    int* src_s = (int*)(sm + 2 * BUF_B);
    int* dst_s = src_s + BM;

    const int tid = threadIdx.x;
    const int wid = tid >> 5;
    const int lane = tid & 31;
    const int g = lane >> 2;
    const int tg = lane & 3;
    const int row0 = blockIdx.x * BM;
    const int col0 = blockIdx.y * BN;
    const int m0 = (wid & 3) * 32;
    const int n0 = (wid >> 2) * 64;

    if (tid < BM) {
        src_s[tid] = src[row0 + tid];
        dst_s[tid] = dst[row0 + tid];
    }

    float acc[2][8][4];
#pragma unroll
    for (int mt = 0; mt < 2; mt++)
#pragma unroll
        for (int nt = 0; nt < 8; nt++)
#pragma unroll
            for (int q = 0; q < 4; q++) acc[mt][nt][q] = 0.f;

    mma_mainloop_db(Eold, Wh, Wl, row0, col0, sm, smb, acc);

    // ---- fused epilogue ----
#pragma unroll
    for (int mt = 0; mt < 2; mt++) {
#pragma unroll
        for (int h = 0; h < 2; h++) {
            int lrow = m0 + mt * 16 + g + h * 8;
            int r = row0 + lrow;
            int s = src_s[lrow];
            int d = dst_s[lrow];
            const float* wsp = xWs + (size_t)s * Uu + col0 + n0;
            const float* wtp = xWt + (size_t)d * Uu + col0 + n0;
            const float* eop = Eold + (size_t)r * Uu + col0 + n0;
            const float* bbp = bel + col0 + n0;
            float* outp = Enew + (size_t)r * Uu + col0 + n0;
#pragma unroll
            for (int nt = 0; nt < 8; nt++) {
                int c = nt * 8 + tg * 2;
                float2 ws = *(const float2*)(wsp + c);
                float2 wt = *(const float2*)(wtp + c);
                float2 eo = *(const float2*)(eop + c);
                float2 bb = *(const float2*)(bbp + c);
                float a0 = acc[mt][nt][h * 2 + 0];
                float a1 = acc[mt][nt][h * 2 + 1];
                float2 v;
                v.x = eo.x + fmaxf(a0 + ws.x + wt.x + bb.x, 0.f);
                v.y = eo.y + fmaxf(a1 + ws.y + wt.y + bb.y, 0.f);
                *(float2*)(outp + c) = v;
            }
        }
    }
}

// ---- tensor-core MLP head: out = prelu([e|a]@Wm1 + bm1) @ Wm2 + bm2 --------
__global__ void __launch_bounds__(256) k_mlp_mma(
    const float* __restrict__ Efin, const float* __restrict__ ain,
    const __nv_bfloat16* __restrict__ W1h, const __nv_bfloat16* __restrict__ W1l,
    const float* __restrict__ Wm1, const float* __restrict__ bm1,
    const float* __restrict__ alpha, const float* __restrict__ Wm2,
    const float* __restrict__ bm2, float* __restrict__ outp)
{
    extern __shared__ __align__(16) unsigned char sm[];
    const uint32_t smb = smem_u32(sm);
    float* red = (float*)(sm + 2 * BUF_B);  // [128][2]

    const int tid = threadIdx.x;
    const int wid = tid >> 5;
    const int lane = tid & 31;
    const int g = lane >> 2;
    const int tg = lane & 3;
    const int row0 = blockIdx.x * BM;
    const int m0 = (wid & 3) * 32;
    const int n0 = (wid >> 2) * 64;

    float acc[2][8][4];
#pragma unroll
    for (int mt = 0; mt < 2; mt++)
#pragma unroll
        for (int nt = 0; nt < 8; nt++)
#pragma unroll
            for (int q = 0; q < 4; q++) acc[mt][nt][q] = 0.f;

    mma_mainloop_db(Efin, W1h, W1l, row0, 0, sm, smb, acc);

    const float al = alpha[0];
    const float* wlp = Wm1 + 256 * 128;
#pragma unroll
    for (int mt = 0; mt < 2; mt++) {
#pragma unroll
        for (int h = 0; h < 2; h++) {
            int lrow = m0 + mt * 16 + g + h * 8;
            float a = ain[row0 + lrow];
            float part = 0.f;
#pragma unroll
            for (int nt = 0; nt < 8; nt++) {
                int c = n0 + nt * 8 + tg * 2;
                float2 wl = *(const float2*)(wlp + c);
                float2 b1 = *(const float2*)(bm1 + c);
                float2 w2 = *(const float2*)(Wm2 + c);
                float h0 = acc[mt][nt][h * 2 + 0] + a * wl.x + b1.x;
                float h1 = acc[mt][nt][h * 2 + 1] + a * wl.y + b1.y;
                h0 = (h0 > 0.f) ? h0 : al * h0;
                h1 = (h1 > 0.f) ? h1 : al * h1;
                part = fmaf(h0, w2.x, part);
                part = fmaf(h1, w2.y, part);
            }
            part += __shfl_xor_sync(0xFFFFFFFFu, part, 1);
            part += __shfl_xor_sync(0xFFFFFFFFu, part, 2);
            if (tg == 0) red[lrow * 2 + (wid >> 2)] = part;
        }
    }
    __syncthreads();
    if (tid < BM)
        outp[row0 + tid] = red[tid * 2] + red[tid * 2 + 1] + bm2[0];
}

// ---- weight pre-split kernels ----------------------------------------------
__global__ void k_prep_we(const float* __restrict__ We)
{
    int t = blockIdx.x * blockDim.x + threadIdx.x;
    if (t >= (Ll + 1) * Uu * Uu) return;
    int l = t >> 16;
    int n = (t >> 8) & 255;
    int k = t & 255;
    float w = We[(size_t)l * Uu * Uu + k * Uu + n];
    __nv_bfloat16 h = __float2bfloat16(w);
    g_WeH[t] = h;
    g_WeL[t] = __float2bfloat16(w - __bfloat162float(h));
}

__global__ void k_prep_wm1(const float* __restrict__ Wm1)
{
    int t = blockIdx.x * blockDim.x + threadIdx.x;
    if (t >= 128 * Uu) return;
    int n = t >> 8;
    int k = t & 255;
    float w = Wm1[k * 128 + n];
    __nv_bfloat16 h = __float2bfloat16(w);
    g_Wm1H[t] = h;
    g_Wm1L[t] = __float2bfloat16(w - __bfloat162float(h));
}

// ======================= fp32 SGEMM path (node gemms) =======================
__device__ __forceinline__ void gemm_mainloop(
    const float* __restrict__ A, const float* __restrict__ B,
    int M, int K, int ldB, int row0, int col0,
    float (*As)[AS_LD], float (*Bs)[BN], float acc[8][8])
{
    const int tid = threadIdx.x;
    const int tx = tid & 15, ty = tid >> 4;
    for (int k0 = 0; k0 < K; k0 += BK) {
#pragma unroll
        for (int v = 0; v < 2; v++) {
            int idx = tid + v * 256;
            int ar = idx >> 2;
            int ak = (idx & 3) << 2;
            int grow = row0 + ar;
            float4 av = make_float4(0.f, 0.f, 0.f, 0.f);
            if (grow < M)
                av = *(const float4*)(A + (size_t)grow * K + k0 + ak);
            As[ak + 0][ar] = av.x;
            As[ak + 1][ar] = av.y;
            As[ak + 2][ar] = av.z;
            As[ak + 3][ar] = av.w;
            int br = idx >> 5;
            int bc = (idx & 31) << 2;
            *(float4*)(&Bs[br][bc]) =
                *(const float4*)(B + (size_t)(k0 + br) * ldB + col0 + bc);
        }
        __syncthreads();
#pragma unroll
        for (int kk = 0; kk < BK; kk++) {
            float af[8], bf[8];
#pragma unroll
            for (int i = 0; i < 8; i++) af[i] = As[kk][ty * 8 + i];
#pragma unroll
            for (int j = 0; j < 8; j++) bf[j] = Bs[kk][tx * 8 + j];
#pragma unroll
            for (int i = 0; i < 8; i++)
#pragma unroll
                for (int j = 0; j < 8; j++)
                    acc[i][j] = fmaf(af[i], bf[j], acc[i][j]);
        }
        __syncthreads();
    }
}

struct Ptr4 {
    const float* B[4];
    float* C[4];
    const float* bias[4];
};

__global__ void __launch_bounds__(256) k_node_gemm(const float* __restrict__ A,
                                                   Ptr4 p, int M)
{
    __shared__ float As[BK][AS_LD];
    __shared__ float Bs[BK][BN];
    float acc[8][8] = {};
    const int z = blockIdx.z;
    const int row0 = blockIdx.x * BM;
    const int col0 = blockIdx.y * BN;
    gemm_mainloop(A, p.B[z], M, Uu, Uu, row0, col0, As, Bs, acc);

    const float* bias = p.bias[z];
    float* C = p.C[z];
    const int tx = threadIdx.x & 15, ty = threadIdx.x >> 4;
#pragma unroll
    for (int i = 0; i < 8; i++) {
        int r = row0 + ty * 8 + i;
        if (r >= M) continue;
#pragma unroll
        for (int j4 = 0; j4 < 8; j4 += 4) {
            int c = col0 + tx * 8 + j4;
            float4 v;
            v.x = acc[i][j4 + 0];
            v.y = acc[i][j4 + 1];
            v.z = acc[i][j4 + 2];
            v.w = acc[i][j4 + 3];
            if (bias) {
                v.x += bias[c + 0];
                v.y += bias[c + 1];
                v.z += bias[c + 2];
                v.w += bias[c + 3];
            }
            *(float4*)(C + (size_t)r * Uu + c) = v;
        }
    }
}

// ---------------- elementwise / scatter kernels ------------------------------
__global__ void k_init_x(const float* __restrict__ pos,
                         const float* __restrict__ Wp,
                         const float* __restrict__ bp)
{
    int t = blockIdx.x * blockDim.x + threadIdx.x;
    if (t >= Nn * Uu) return;
    int i = t >> 8, j = t & 255;
    g_x[t] = fmaf(pos[2 * i], Wp[j], fmaf(pos[2 * i + 1], Wp[Uu + j], bp[j]));
}

__global__ void k_init_e(const float* __restrict__ a,
                         const float* __restrict__ Wa,
                         const float* __restrict__ ba,
                         float* __restrict__ e)
{
    int t = blockIdx.x * blockDim.x + threadIdx.x;
    if (t >= Ee * (Uu / 4)) return;
    int i = t >> 6;
    int j = (t & 63) << 2;
    float av = a[i];
    float4 w = *(const float4*)(Wa + j);
    float4 b = *(const float4*)(ba + j);
    float4 v;
    v.x = fmaf(av, w.x, b.x);
    v.y = fmaf(av, w.y, b.y);
    v.z = fmaf(av, w.z, b.z);
    v.w = fmaf(av, w.w, b.w);
    *(float4*)(e + (size_t)i * Uu + j) = v;
}

__global__ void k_zero_agg()
{
    int t = blockIdx.x * blockDim.x + threadIdx.x;
    if (t >= Nn * Uu / 4) return;
    *(float4*)(g_agg + (size_t)t * 4) = make_float4(0.f, 0.f, 0.f, 0.f);
}

__global__ void k_msg(const float* __restrict__ e,
                      const float* __restrict__ xW2,
                      const int* __restrict__ src,
                      const int* __restrict__ dst)
{
    int t = blockIdx.x * blockDim.x + threadIdx.x;
    if (t >= Ee * (Uu / 4)) return;
    int i = t >> 6;
    int j = (t & 63) << 2;
    float4 ev = *(const float4*)(e + (size_t)i * Uu + j);
    int s = __ldg(src + i);
    int d = __ldg(dst + i);
    float4 xv = *(const float4*)(xW2 + (size_t)s * Uu + j);
    float4 m;
    m.x = xv.x / (1.f + __expf(-ev.x));
    m.y = xv.y / (1.f + __expf(-ev.y));
    m.z = xv.z / (1.f + __expf(-ev.z));
    m.w = xv.w / (1.f + __expf(-ev.w));
    float* ap = g_agg + (size_t)d * Uu + j;
    atomicAdd(ap + 0, m.x);
    atomicAdd(ap + 1, m.y);
    atomicAdd(ap + 2, m.z);
    atomicAdd(ap + 3, m.w);
}

__global__ void k_node_update()
{
    int t = blockIdx.x * blockDim.x + threadIdx.x;
    if (t >= Nn * Uu) return;
    g_x[t] += fmaxf(g_xW1[t] + g_agg[t], 0.f);
}

// ---------------- host driver ------------------------------------------------
extern "C" void kernel_launch(void* const* d_in, const int* in_sizes, int n_in,
                              void* d_out, int out_size)
{
    const float* pos   = (const float*)d_in[0];
    const float* ain   = (const float*)d_in[1];
    const int*   eidx  = (const int*)d_in[2];
    const float* Wp    = (const float*)d_in[3];
    const float* bp    = (const float*)d_in[4];
    const float* Wa    = (const float*)d_in[5];
    const float* ba    = (const float*)d_in[6];
    const float* W1    = (const float*)d_in[7];
    const float* b1    = (const float*)d_in[8];
    const float* W2    = (const float*)d_in[9];
    const float* b2    = (const float*)d_in[10];
    const float* We    = (const float*)d_in[11];
    const float* be    = (const float*)d_in[12];
    const float* Ws    = (const float*)d_in[13];
    const float* Wt    = (const float*)d_in[14];
    const float* Wm1   = (const float*)d_in[15];
    const float* bm1   = (const float*)d_in[16];
    const float* alpha = (const float*)d_in[17];
    const float* Wm2   = (const float*)d_in[18];
    const float* bm2   = (const float*)d_in[19];
    float* outp = (float*)d_out;

    const int* src = eidx;
    const int* dst = eidx + Ee;

    float *px, *pxW1, *pxW2, *pxWs, *pxWt, *pe0, *pe1;
    __nv_bfloat16 *pWH, *pWL, *pM1H, *pM1L;
    cudaGetSymbolAddress((void**)&px,   g_x);
    cudaGetSymbolAddress((void**)&pxW1, g_xW1);
    cudaGetSymbolAddress((void**)&pxW2, g_xW2);
    cudaGetSymbolAddress((void**)&pxWs, g_xWs);
    cudaGetSymbolAddress((void**)&pxWt, g_xWt);
    cudaGetSymbolAddress((void**)&pe0,  g_e0);
    cudaGetSymbolAddress((void**)&pe1,  g_e1);
    cudaGetSymbolAddress((void**)&pWH,  g_WeH);
    cudaGetSymbolAddress((void**)&pWL,  g_WeL);
    cudaGetSymbolAddress((void**)&pM1H, g_Wm1H);
    cudaGetSymbolAddress((void**)&pM1L, g_Wm1L);

    cudaFuncSetAttribute(k_edge_mma, cudaFuncAttributeMaxDynamicSharedMemorySize,
                         SMEMB);
    cudaFuncSetAttribute(k_mlp_mma, cudaFuncAttributeMaxDynamicSharedMemorySize,
                         SMEMB);

    const int nodeRowBlocks = (Nn + BM - 1) / BM;
    const int ew_grid = (Ee * (Uu / 4) + 255) / 256;

    k_init_x<<<(Nn * Uu + 255) / 256, 256>>>(pos, Wp, bp);
    k_init_e<<<ew_grid, 256>>>(ain, Wa, ba, pe0);
    k_prep_we<<<((Ll + 1) * Uu * Uu + 255) / 256, 256>>>(We);
    k_prep_wm1<<<(128 * Uu + 255) / 256, 256>>>(Wm1);

    float* ecur = pe0;
    float* enxt = pe1;

    for (int l = 0; l < Ll; l++) {
        Ptr4 p;
        p.B[0] = W1 + (size_t)l * Uu * Uu;
        p.B[1] = W2 + (size_t)l * Uu * Uu;
        p.B[2] = Ws + (size_t)l * Uu * Uu;
        p.B[3] = Wt + (size_t)l * Uu * Uu;
        p.C[0] = pxW1; p.C[1] = pxW2; p.C[2] = pxWs; p.C[3] = pxWt;
        p.bias[0] = b1 + (size_t)l * Uu;
        p.bias[1] = b2 + (size_t)l * Uu;
        p.bias[2] = nullptr;
        p.bias[3] = nullptr;
        k_node_gemm<<<dim3(nodeRowBlocks, 2, 4), 256>>>(px, p, Nn);

        k_zero_agg<<<(Nn * Uu / 4 + 255) / 256, 256>>>();
        k_msg<<<ew_grid, 256>>>(ecur, pxW2, src, dst);

        k_edge_mma<<<dim3(Ee / BM, 2), 256, SMEMB>>>(
            ecur, pWH + (size_t)l * Uu * Uu, pWL + (size_t)l * Uu * Uu,
            be + (size_t)l * Uu, pxWs, pxWt, src, dst, enxt);

        k_node_update<<<(Nn * Uu + 255) / 256, 256>>>();

        float* tmp = ecur; ecur = enxt; enxt = tmp;
    }

    // final edge update (l = L)
    {
        Ptr4 p;
        p.B[0] = Ws + (size_t)Ll * Uu * Uu;
        p.B[1] = Wt + (size_t)Ll * Uu * Uu;
        p.B[2] = p.B[0]; p.B[3] = p.B[0];
        p.C[0] = pxWs; p.C[1] = pxWt; p.C[2] = pxWs; p.C[3] = pxWs;
        p.bias[0] = nullptr; p.bias[1] = nullptr;
        p.bias[2] = nullptr; p.bias[3] = nullptr;
        k_node_gemm<<<dim3(nodeRowBlocks, 2, 2), 256>>>(px, p, Nn);

        k_edge_mma<<<dim3(Ee / BM, 2), 256, SMEMB>>>(
            ecur, pWH + (size_t)Ll * Uu * Uu, pWL + (size_t)Ll * Uu * Uu,
            be + (size_t)Ll * Uu, pxWs, pxWt, src, dst, enxt);
        float* tmp = ecur; ecur = enxt; enxt = tmp;
    }

    k_mlp_mma<<<Ee / BM, 256, SMEMB>>>(ecur, ain, pM1H, pM1L, Wm1, bm1,
                                       alpha, Wm2, bm2, outp);
}

// round 16
// speedup vs baseline: 1.4451x; 1.0267x over previous
#include <cuda_runtime.h>
#include <cuda_bf16.h>
#include <cstdint>
#include <cstddef>

#define Nn 10000
#define Ee 320000
#define Uu 256
#define Ll 3

#define BM 128
#define BN 128

// ---------------- scratch (device globals; no allocations allowed) ----------
__device__ float g_x[Nn * Uu];
__device__ float g_xW1[Nn * Uu];
__device__ float g_xW2[Nn * Uu];
__device__ float g_xWs[Nn * Uu];
__device__ float g_xWt[Nn * Uu];
__device__ float g_agg[Nn * Uu];
__device__ float g_e0[(size_t)Ee * Uu];
__device__ float g_e1[(size_t)Ee * Uu];
// pre-split edge weights, [l][n][k] K-major bf16 (hi & lo parts)
__device__ __nv_bfloat16 g_WeH[(Ll + 1) * Uu * Uu];
__device__ __nv_bfloat16 g_WeL[(Ll + 1) * Uu * Uu];
// pre-split MLP weight Wm1[0:256,:] -> [n=128][k=256] K-major hi/lo
__device__ __nv_bfloat16 g_Wm1H[128 * Uu];
__device__ __nv_bfloat16 g_Wm1L[128 * Uu];
// pre-split node weights: 14 slots (l*4 + {W1,W2,Ws,Wt}; 12=WsL, 13=WtL)
__device__ __nv_bfloat16 g_WnH[14 * Uu * Uu];
__device__ __nv_bfloat16 g_WnL[14 * Uu * Uu];

// ---------------- helpers ----------------------------------------------------
__device__ __forceinline__ uint32_t smem_u32(const void* p) {
    uint32_t a;
    asm("{ .reg .u64 t; cvta.to.shared.u64 t, %1; cvt.u32.u64 %0, t; }"
        : "=r"(a) : "l"(p));
    return a;
}

__device__ __forceinline__ void cp16(uint32_t s, const void* g) {
    asm volatile("cp.async.cg.shared.global [%0], [%1], 16;" :: "r"(s), "l"(g));
}
#define CP_COMMIT() asm volatile("cp.async.commit_group;" ::: "memory")
#define CP_WAIT0()  asm volatile("cp.async.wait_group 0;" ::: "memory")

__device__ __forceinline__ void split2(float a, float b, uint32_t& h, uint32_t& l)
{
    __nv_bfloat16 ha = __float2bfloat16(a);
    __nv_bfloat16 hb = __float2bfloat16(b);
    __nv_bfloat162 hp;
    hp.x = ha; hp.y = hb;
    h = *reinterpret_cast<uint32_t*>(&hp);
    __nv_bfloat162 lp;
    lp.x = __float2bfloat16(a - __bfloat162float(ha));
    lp.y = __float2bfloat16(b - __bfloat162float(hb));
    l = *reinterpret_cast<uint32_t*>(&lp);
}

__device__ __forceinline__ void mma16816(float* c, const uint32_t* a,
                                         const uint32_t* b)
{
    asm volatile(
        "mma.sync.aligned.m16n8k16.row.col.f32.bf16.bf16.f32 "
        "{%0,%1,%2,%3}, {%4,%5,%6,%7}, {%8,%9}, {%0,%1,%2,%3};"
        : "+f"(c[0]), "+f"(c[1]), "+f"(c[2]), "+f"(c[3])
        : "r"(a[0]), "r"(a[1]), "r"(a[2]), "r"(a[3]), "r"(b[0]), "r"(b[1]));
}

// SMEM row stride 40 bf16 (80 B): conflict-free frag LDS (proven in R9).
#define SLD 40
#define TILE_B 10240            // 128 * 40 * 2 bytes
#define BUF_B  (4 * TILE_B)     // Ah, Al, Bh, Bl per buffer
#define SMEMB  (2 * BUF_B + 1024)

// ---- double-buffered 3-pass mainloop (row-clamped):
//      acc += Ah@Bh^T + Ah@Bl^T + Al@Bh^T
__device__ __forceinline__ void mma_mainloop_db(
    const float* __restrict__ A,
    const __nv_bfloat16* __restrict__ Bh, const __nv_bfloat16* __restrict__ Bl,
    int row0, int col0, int Mrows, unsigned char* sm, uint32_t smb,
    float acc[2][8][4])
{
    const int tid = threadIdx.x;
    const int wid = tid >> 5;
    const int lane = tid & 31;
    const int g = lane >> 2;
    const int tg = lane & 3;
    const int m0 = (wid & 3) * 32;
    const int n0 = (wid >> 2) * 64;
    const int frow = tid >> 1;
    const int fkh = (tid & 1) * 16;

    int agrow = row0 + frow;
    if (agrow >= Mrows) agrow = Mrows - 1;
    const float4* arow = (const float4*)(A + (size_t)agrow * Uu);
    const __nv_bfloat16* bhrow = Bh + (size_t)(col0 + frow) * Uu;
    const __nv_bfloat16* blrow = Bl + (size_t)(col0 + frow) * Uu;

    const uint32_t sdst = smb + frow * 80 + fkh * 2;
    const uint32_t arow_off = frow * 80 + fkh * 2;

    float4 aPF[4];
#pragma unroll
    for (int q = 0; q < 4; q++) aPF[q] = arow[(fkh >> 2) + q];
    {
        uint32_t db = sdst + 2 * TILE_B;
        cp16(db,      bhrow + fkh);
        cp16(db + 16, bhrow + fkh + 8);
        uint32_t dl = db + TILE_B;
        cp16(dl,      blrow + fkh);
        cp16(dl + 16, blrow + fkh + 8);
        CP_COMMIT();
    }
#pragma unroll
    for (int q = 0; q < 4; q++) {
        uint32_t h0, l0, h1, l1;
        split2(aPF[q].x, aPF[q].y, h0, l0);
        split2(aPF[q].z, aPF[q].w, h1, l1);
        *(uint32_t*)(sm + arow_off + (4 * q) * 2)              = h0;
        *(uint32_t*)(sm + arow_off + (4 * q + 2) * 2)          = h1;
        *(uint32_t*)(sm + TILE_B + arow_off + (4 * q) * 2)     = l0;
        *(uint32_t*)(sm + TILE_B + arow_off + (4 * q + 2) * 2) = l1;
    }
    CP_WAIT0();
    __syncthreads();

    for (int kc = 0; kc < 8; kc++) {
        const int cur = kc & 1;
        if (kc < 7) {
            const int nk = (kc + 1) * 32;
#pragma unroll
            for (int q = 0; q < 4; q++) aPF[q] = arow[((nk + fkh) >> 2) + q];
            uint32_t db = sdst + (cur ^ 1) * BUF_B + 2 * TILE_B;
            cp16(db,      bhrow + nk + fkh);
            cp16(db + 16, bhrow + nk + fkh + 8);
            uint32_t dl = db + TILE_B;
            cp16(dl,      blrow + nk + fkh);
            cp16(dl + 16, blrow + nk + fkh + 8);
            CP_COMMIT();
        }

        const __nv_bfloat16 (*ApH)[SLD] =
            (const __nv_bfloat16 (*)[SLD])(sm + cur * BUF_B);
        const __nv_bfloat16 (*ApL)[SLD] =
            (const __nv_bfloat16 (*)[SLD])(sm + cur * BUF_B + TILE_B);
        const __nv_bfloat16 (*BpH)[SLD] =
            (const __nv_bfloat16 (*)[SLD])(sm + cur * BUF_B + 2 * TILE_B);
        const __nv_bfloat16 (*BpL)[SLD] =
            (const __nv_bfloat16 (*)[SLD])(sm + cur * BUF_B + 3 * TILE_B);

#pragma unroll
        for (int pass = 0; pass < 3; pass++) {
            const __nv_bfloat16 (*Ap)[SLD] = (pass == 2) ? ApL : ApH;
            const __nv_bfloat16 (*Bp)[SLD] = (pass == 1) ? BpL : BpH;
#pragma unroll
            for (int ks = 0; ks < 2; ks++) {
                const int kb = ks * 16 + tg * 2;
                uint32_t a[2][4], b[8][2];
#pragma unroll
                for (int mt = 0; mt < 2; mt++) {
                    int mr = m0 + mt * 16 + g;
                    a[mt][0] = *(const uint32_t*)&Ap[mr][kb];
                    a[mt][1] = *(const uint32_t*)&Ap[mr + 8][kb];
                    a[mt][2] = *(const uint32_t*)&Ap[mr][kb + 8];
                    a[mt][3] = *(const uint32_t*)&Ap[mr + 8][kb + 8];
                }
#pragma unroll
                for (int nt = 0; nt < 8; nt++) {
                    int nr = n0 + nt * 8 + g;
                    b[nt][0] = *(const uint32_t*)&Bp[nr][kb];
                    b[nt][1] = *(const uint32_t*)&Bp[nr][kb + 8];
                }
#pragma unroll
                for (int mt = 0; mt < 2; mt++)
#pragma unroll
                    for (int nt = 0; nt < 8; nt++)
                        mma16816(acc[mt][nt], a[mt], b[nt]);
            }
        }

        if (kc < 7) {
            unsigned char* an = sm + (cur ^ 1) * BUF_B;
#pragma unroll
            for (int q = 0; q < 4; q++) {
                uint32_t h0, l0, h1, l1;
                split2(aPF[q].x, aPF[q].y, h0, l0);
                split2(aPF[q].z, aPF[q].w, h1, l1);
                *(uint32_t*)(an + arow_off + (4 * q) * 2)              = h0;
                *(uint32_t*)(an + arow_off + (4 * q + 2) * 2)          = h1;
                *(uint32_t*)(an + TILE_B + arow_off + (4 * q) * 2)     = l0;
                *(uint32_t*)(an + TILE_B + arow_off + (4 * q + 2) * 2) = l1;
            }
            CP_WAIT0();
        }
        __syncthreads();
    }
}

// ---- tensor-core fused edge update + (optional) message scatter:
//   Enew = Eold + relu(Eold@We + xWs[src] + xWt[dst] + be)
//   if xW2: g_agg[dst] += sigmoid(Eold) * xW2[src]   (the layer's msg pass)
__global__ void __launch_bounds__(256) k_edge_mma(
    const float* __restrict__ Eold,
    const __nv_bfloat16* __restrict__ Wh, const __nv_bfloat16* __restrict__ Wl,
    const float* __restrict__ bel,
    const float* __restrict__ xWs, const float* __restrict__ xWt,
    const float* __restrict__ xW2,  // nullptr => no msg fusion (final layer)
    const int* __restrict__ src, const int* __restrict__ dst,
    float* __restrict__ Enew)
{
    extern __shared__ __align__(16) unsigned char sm[];
    const uint32_t smb = smem_u32(sm);
    int* src_s = (int*)(sm + 2 * BUF_B);
    int* dst_s = src_s + BM;

    const int tid = threadIdx.x;
    const int wid = tid >> 5;
    const int lane = tid & 31;
    const int g = lane >> 2;
    const int tg = lane & 3;
    const int row0 = blockIdx.x * BM;
    const int col0 = blockIdx.y * BN;
    const int m0 = (wid & 3) * 32;
    const int n0 = (wid >> 2) * 64;

    if (tid < BM) {
        src_s[tid] = src[row0 + tid];
        dst_s[tid] = dst[row0 + tid];
    }

    float acc[2][8][4];
#pragma unroll
    for (int mt = 0; mt < 2; mt++)
#pragma unroll
        for (int nt = 0; nt < 8; nt++)
#pragma unroll
            for (int q = 0; q < 4; q++) acc[mt][nt][q] = 0.f;

    mma_mainloop_db(Eold, Wh, Wl, row0, col0, Ee, sm, smb, acc);

    // ---- fused epilogue ----
#pragma unroll
    for (int mt = 0; mt < 2; mt++) {
#pragma unroll
        for (int h = 0; h < 2; h++) {
            int lrow = m0 + mt * 16 + g + h * 8;
            int r = row0 + lrow;
            int s = src_s[lrow];
            int d = dst_s[lrow];
            const float* wsp = xWs + (size_t)s * Uu + col0 + n0;
            const float* wtp = xWt + (size_t)d * Uu + col0 + n0;
            const float* eop = Eold + (size_t)r * Uu + col0 + n0;
            const float* bbp = bel + col0 + n0;
            float* outp = Enew + (size_t)r * Uu + col0 + n0;
            const float* x2p =
                xW2 ? xW2 + (size_t)s * Uu + col0 + n0 : nullptr;
            float* aggp = g_agg + (size_t)d * Uu + col0 + n0;
#pragma unroll
            for (int nt = 0; nt < 8; nt++) {
                int c = nt * 8 + tg * 2;
                float2 ws = *(const float2*)(wsp + c);
                float2 wt = *(const float2*)(wtp + c);
                float2 eo = *(const float2*)(eop + c);
                float2 bb = *(const float2*)(bbp + c);
                float a0 = acc[mt][nt][h * 2 + 0];
                float a1 = acc[mt][nt][h * 2 + 1];
                float2 v;
                v.x = eo.x + fmaxf(a0 + ws.x + wt.x + bb.x, 0.f);
                v.y = eo.y + fmaxf(a1 + ws.y + wt.y + bb.y, 0.f);
                *(float2*)(outp + c) = v;
                if (xW2) {
                    float2 xv = *(const float2*)(x2p + c);
                    atomicAdd(aggp + c,     xv.x / (1.f + __expf(-eo.x)));
                    atomicAdd(aggp + c + 1, xv.y / (1.f + __expf(-eo.y)));
                }
            }
        }
    }
}

// ---- tensor-core node GEMMs: C[z] = x @ W[z] (+ bias[z]) -------------------
struct NodePtrs {
    const __nv_bfloat16* Bh[4];
    const __nv_bfloat16* Bl[4];
    const float* bias[4];
    float* C[4];
};

__global__ void __launch_bounds__(256) k_node_mma(const float* __restrict__ A,
                                                  NodePtrs p)
{
    extern __shared__ __align__(16) unsigned char sm[];
    const uint32_t smb = smem_u32(sm);

    const int tid = threadIdx.x;
    const int wid = tid >> 5;
    const int lane = tid & 31;
    const int g = lane >> 2;
    const int tg = lane & 3;
    const int z = blockIdx.z;
    const int row0 = blockIdx.x * BM;
    const int col0 = blockIdx.y * BN;
    const int m0 = (wid & 3) * 32;
    const int n0 = (wid >> 2) * 64;

    float acc[2][8][4];
#pragma unroll
    for (int mt = 0; mt < 2; mt++)
#pragma unroll
        for (int nt = 0; nt < 8; nt++)
#pragma unroll
            for (int q = 0; q < 4; q++) acc[mt][nt][q] = 0.f;

    mma_mainloop_db(A, p.Bh[z], p.Bl[z], row0, col0, Nn, sm, smb, acc);

    const float* bias = p.bias[z];
    float* C = p.C[z];
#pragma unroll
    for (int mt = 0; mt < 2; mt++) {
#pragma unroll
        for (int h = 0; h < 2; h++) {
            int r = row0 + m0 + mt * 16 + g + h * 8;
            if (r >= Nn) continue;
            float* outp = C + (size_t)r * Uu + col0 + n0;
            const float* bbp = bias ? bias + col0 + n0 : nullptr;
#pragma unroll
            for (int nt = 0; nt < 8; nt++) {
                int c = nt * 8 + tg * 2;
                float2 v;
                v.x = acc[mt][nt][h * 2 + 0];
                v.y = acc[mt][nt][h * 2 + 1];
                if (bias) {
                    float2 bb = *(const float2*)(bbp + c);
                    v.x += bb.x;
                    v.y += bb.y;
                }
                *(float2*)(outp + c) = v;
            }
        }
    }
}

// ---- tensor-core MLP head: out = prelu([e|a]@Wm1 + bm1) @ Wm2 + bm2 --------
__global__ void __launch_bounds__(256) k_mlp_mma(
    const float* __restrict__ Efin, const float* __restrict__ ain,
    const __nv_bfloat16* __restrict__ W1h, const __nv_bfloat16* __restrict__ W1l,
    const float* __restrict__ Wm1, const float* __restrict__ bm1,
    const float* __restrict__ alpha, const float* __restrict__ Wm2,
    const float* __restrict__ bm2, float* __restrict__ outp)
{
    extern __shared__ __align__(16) unsigned char sm[];
    const uint32_t smb = smem_u32(sm);
    float* red = (float*)(sm + 2 * BUF_B);  // [128][2]

    const int tid = threadIdx.x;
    const int wid = tid >> 5;
    const int lane = tid & 31;
    const int g = lane >> 2;
    const int tg = lane & 3;
    const int row0 = blockIdx.x * BM;
    const int m0 = (wid & 3) * 32;
    const int n0 = (wid >> 2) * 64;

    float acc[2][8][4];
#pragma unroll
    for (int mt = 0; mt < 2; mt++)
#pragma unroll
        for (int nt = 0; nt < 8; nt++)
#pragma unroll
            for (int q = 0; q < 4; q++) acc[mt][nt][q] = 0.f;

    mma_mainloop_db(Efin, W1h, W1l, row0, 0, Ee, sm, smb, acc);

    const float al = alpha[0];
    const float* wlp = Wm1 + 256 * 128;
#pragma unroll
    for (int mt = 0; mt < 2; mt++) {
#pragma unroll
        for (int h = 0; h < 2; h++) {
            int lrow = m0 + mt * 16 + g + h * 8;
            float a = ain[row0 + lrow];
            float part = 0.f;
#pragma unroll
            for (int nt = 0; nt < 8; nt++) {
                int c = n0 + nt * 8 + tg * 2;
                float2 wl = *(const float2*)(wlp + c);
                float2 b1 = *(const float2*)(bm1 + c);
                float2 w2 = *(const float2*)(Wm2 + c);
                float h0 = acc[mt][nt][h * 2 + 0] + a * wl.x + b1.x;
                float h1 = acc[mt][nt][h * 2 + 1] + a * wl.y + b1.y;
                h0 = (h0 > 0.f) ? h0 : al * h0;
                h1 = (h1 > 0.f) ? h1 : al * h1;
                part = fmaf(h0, w2.x, part);
                part = fmaf(h1, w2.y, part);
            }
            part += __shfl_xor_sync(0xFFFFFFFFu, part, 1);
            part += __shfl_xor_sync(0xFFFFFFFFu, part, 2);
            if (tg == 0) red[lrow * 2 + (wid >> 2)] = part;
        }
    }
    __syncthreads();
    if (tid < BM)
        outp[row0 + tid] = red[tid * 2] + red[tid * 2 + 1] + bm2[0];
}

// ---- weight pre-split kernels ----------------------------------------------
__global__ void k_prep_we(const float* __restrict__ We)
{
    int t = blockIdx.x * blockDim.x + threadIdx.x;
    if (t >= (Ll + 1) * Uu * Uu) return;
    int l = t >> 16;
    int n = (t >> 8) & 255;
    int k = t & 255;
    float w = We[(size_t)l * Uu * Uu + k * Uu + n];
    __nv_bfloat16 h = __float2bfloat16(w);
    g_WeH[t] = h;
    g_WeL[t] = __float2bfloat16(w - __bfloat162float(h));
}

__global__ void k_prep_wm1(const float* __restrict__ Wm1)
{
    int t = blockIdx.x * blockDim.x + threadIdx.x;
    if (t >= 128 * Uu) return;
    int n = t >> 8;
    int k = t & 255;
    float w = Wm1[k * 128 + n];
    __nv_bfloat16 h = __float2bfloat16(w);
    g_Wm1H[t] = h;
    g_Wm1L[t] = __float2bfloat16(w - __bfloat162float(h));
}

__global__ void k_prep_wn(const float* __restrict__ W1,
                          const float* __restrict__ W2,
                          const float* __restrict__ Ws,
                          const float* __restrict__ Wt)
{
    int t = blockIdx.x * blockDim.x + threadIdx.x;
    if (t >= 14 * Uu * Uu) return;
    int slot = t >> 16;
    int n = (t >> 8) & 255;
    int k = t & 255;
    const float* base;
    if (slot < 12) {
        int l = slot >> 2;
        int which = slot & 3;
        base = (which == 0 ? W1 : which == 1 ? W2 : which == 2 ? Ws : Wt) +
               (size_t)l * Uu * Uu;
    } else {
        base = (slot == 12 ? Ws : Wt) + (size_t)Ll * Uu * Uu;
    }
    float w = base[k * Uu + n];
    __nv_bfloat16 h = __float2bfloat16(w);
    g_WnH[t] = h;
    g_WnL[t] = __float2bfloat16(w - __bfloat162float(h));
}

// ---------------- elementwise kernels ----------------------------------------
__global__ void k_init_x(const float* __restrict__ pos,
                         const float* __restrict__ Wp,
                         const float* __restrict__ bp)
{
    int t = blockIdx.x * blockDim.x + threadIdx.x;
    if (t >= Nn * Uu) return;
    int i = t >> 8, j = t & 255;
    g_x[t] = fmaf(pos[2 * i], Wp[j], fmaf(pos[2 * i + 1], Wp[Uu + j], bp[j]));
}

__global__ void k_init_e(const float* __restrict__ a,
                         const float* __restrict__ Wa,
                         const float* __restrict__ ba,
                         float* __restrict__ e)
{
    int t = blockIdx.x * blockDim.x + threadIdx.x;
    if (t >= Ee * (Uu / 4)) return;
    int i = t >> 6;
    int j = (t & 63) << 2;
    float av = a[i];
    float4 w = *(const float4*)(Wa + j);
    float4 b = *(const float4*)(ba + j);
    float4 v;
    v.x = fmaf(av, w.x, b.x);
    v.y = fmaf(av, w.y, b.y);
    v.z = fmaf(av, w.z, b.z);
    v.w = fmaf(av, w.w, b.w);
    *(float4*)(e + (size_t)i * Uu + j) = v;
}

__global__ void k_zero_agg()
{
    int t = blockIdx.x * blockDim.x + threadIdx.x;
    if (t >= Nn * Uu / 4) return;
    *(float4*)(g_agg + (size_t)t * 4) = make_float4(0.f, 0.f, 0.f, 0.f);
}

__global__ void k_node_update()
{
    int t = blockIdx.x * blockDim.x + threadIdx.x;
    if (t >= Nn * Uu) return;
    g_x[t] += fmaxf(g_xW1[t] + g_agg[t], 0.f);
}

// ---------------- host driver ------------------------------------------------
extern "C" void kernel_launch(void* const* d_in, const int* in_sizes, int n_in,
                              void* d_out, int out_size)
{
    const float* pos   = (const float*)d_in[0];
    const float* ain   = (const float*)d_in[1];
    const int*   eidx  = (const int*)d_in[2];
    const float* Wp    = (const float*)d_in[3];
    const float* bp    = (const float*)d_in[4];
    const float* Wa    = (const float*)d_in[5];
    const float* ba    = (const float*)d_in[6];
    const float* W1    = (const float*)d_in[7];
    const float* b1    = (const float*)d_in[8];
    const float* W2    = (const float*)d_in[9];
    const float* b2    = (const float*)d_in[10];
    const float* We    = (const float*)d_in[11];
    const float* be    = (const float*)d_in[12];
    const float* Ws    = (const float*)d_in[13];
    const float* Wt    = (const float*)d_in[14];
    const float* Wm1   = (const float*)d_in[15];
    const float* bm1   = (const float*)d_in[16];
    const float* alpha = (const float*)d_in[17];
    const float* Wm2   = (const float*)d_in[18];
    const float* bm2   = (const float*)d_in[19];
    float* outp = (float*)d_out;

    const int* src = eidx;
    const int* dst = eidx + Ee;

    float *px, *pxW1, *pxW2, *pxWs, *pxWt, *pe0, *pe1;
    __nv_bfloat16 *pWH, *pWL, *pM1H, *pM1L, *pWnH, *pWnL;
    cudaGetSymbolAddress((void**)&px,   g_x);
    cudaGetSymbolAddress((void**)&pxW1, g_xW1);
    cudaGetSymbolAddress((void**)&pxW2, g_xW2);
    cudaGetSymbolAddress((void**)&pxWs, g_xWs);
    cudaGetSymbolAddress((void**)&pxWt, g_xWt);
    cudaGetSymbolAddress((void**)&pe0,  g_e0);
    cudaGetSymbolAddress((void**)&pe1,  g_e1);
    cudaGetSymbolAddress((void**)&pWH,  g_WeH);
    cudaGetSymbolAddress((void**)&pWL,  g_WeL);
    cudaGetSymbolAddress((void**)&pM1H, g_Wm1H);
    cudaGetSymbolAddress((void**)&pM1L, g_Wm1L);
    cudaGetSymbolAddress((void**)&pWnH, g_WnH);
    cudaGetSymbolAddress((void**)&pWnL, g_WnL);

    cudaFuncSetAttribute(k_edge_mma, cudaFuncAttributeMaxDynamicSharedMemorySize,
                         SMEMB);
    cudaFuncSetAttribute(k_node_mma, cudaFuncAttributeMaxDynamicSharedMemorySize,
                         SMEMB);
    cudaFuncSetAttribute(k_mlp_mma, cudaFuncAttributeMaxDynamicSharedMemorySize,
                         SMEMB);

    const int nodeRowBlocks = (Nn + BM - 1) / BM;  // 79

    k_init_x<<<(Nn * Uu + 255) / 256, 256>>>(pos, Wp, bp);
    k_init_e<<<(Ee * (Uu / 4) + 255) / 256, 256>>>(ain, Wa, ba, pe0);
    k_prep_we<<<((Ll + 1) * Uu * Uu + 255) / 256, 256>>>(We);
    k_prep_wm1<<<(128 * Uu + 255) / 256, 256>>>(Wm1);
    k_prep_wn<<<(14 * Uu * Uu + 255) / 256, 256>>>(W1, W2, Ws, Wt);

    float* ecur = pe0;
    float* enxt = pe1;

    for (int l = 0; l < Ll; l++) {
        NodePtrs p;
        const int s0 = l * 4;
        for (int z = 0; z < 4; z++) {
            p.Bh[z] = pWnH + (size_t)(s0 + z) * Uu * Uu;
            p.Bl[z] = pWnL + (size_t)(s0 + z) * Uu * Uu;
        }
        p.bias[0] = b1 + (size_t)l * Uu;
        p.bias[1] = b2 + (size_t)l * Uu;
        p.bias[2] = nullptr;
        p.bias[3] = nullptr;
        p.C[0] = pxW1; p.C[1] = pxW2; p.C[2] = pxWs; p.C[3] = pxWt;
        k_node_mma<<<dim3(nodeRowBlocks, 2, 4), 256, SMEMB>>>(px, p);

        k_zero_agg<<<(Nn * Uu / 4 + 255) / 256, 256>>>();

        k_edge_mma<<<dim3(Ee / BM, 2), 256, SMEMB>>>(
            ecur, pWH + (size_t)l * Uu * Uu, pWL + (size_t)l * Uu * Uu,
            be + (size_t)l * Uu, pxWs, pxWt, pxW2, src, dst, enxt);

        k_node_update<<<(Nn * Uu + 255) / 256, 256>>>();

        float* tmp = ecur; ecur = enxt; enxt = tmp;
    }

    // final edge update (l = L): no msg fusion
    {
        NodePtrs p;
        p.Bh[0] = pWnH + (size_t)12 * Uu * Uu;
        p.Bl[0] = pWnL + (size_t)12 * Uu * Uu;
        p.Bh[1] = pWnH + (size_t)13 * Uu * Uu;
        p.Bl[1] = pWnL + (size_t)13 * Uu * Uu;
        p.Bh[2] = p.Bh[0]; p.Bl[2] = p.Bl[0];
        p.Bh[3] = p.Bh[0]; p.Bl[3] = p.Bl[0];
        p.bias[0] = nullptr; p.bias[1] = nullptr;
        p.bias[2] = nullptr; p.bias[3] = nullptr;
        p.C[0] = pxWs; p.C[1] = pxWt; p.C[2] = pxWs; p.C[3] = pxWs;
        k_node_mma<<<dim3(nodeRowBlocks, 2, 2), 256, SMEMB>>>(px, p);

        k_edge_mma<<<dim3(Ee / BM, 2), 256, SMEMB>>>(
            ecur, pWH + (size_t)Ll * Uu * Uu, pWL + (size_t)Ll * Uu * Uu,
            be + (size_t)Ll * Uu, pxWs, pxWt, nullptr, src, dst, enxt);
        float* tmp = ecur; ecur = enxt; enxt = tmp;
    }

    k_mlp_mma<<<Ee / BM, 256, SMEMB>>>(ecur, ain, pM1H, pM1L, Wm1, bm1,
                                       alpha, Wm2, bm2, outp);
}

// round 17
// speedup vs baseline: 1.5359x; 1.0628x over previous
#include <cuda_runtime.h>
#include <cuda_bf16.h>
#include <cstdint>
#include <cstddef>

#define Nn 10000
#define Ee 320000
#define Uu 256
#define Ll 3

#define BM 128
#define BN 128

// ---------------- scratch (device globals; no allocations allowed) ----------
__device__ float g_x[Nn * Uu];
__device__ float g_xW1[Nn * Uu];
__device__ float g_xW2[Nn * Uu];
__device__ float g_xWs[Nn * Uu];
__device__ float g_xWt[Nn * Uu];
__device__ float g_e0[(size_t)Ee * Uu];
__device__ float g_e1[(size_t)Ee * Uu];
// CSR (dst-sorted) edge permutation
__device__ int g_cnt[Nn];
__device__ int g_rowptr[Nn + 1];
__device__ int g_off[Nn];
__device__ int g_perm[Ee];
// pre-split edge weights, [l][n][k] K-major bf16 (hi & lo parts)
__device__ __nv_bfloat16 g_WeH[(Ll + 1) * Uu * Uu];
__device__ __nv_bfloat16 g_WeL[(Ll + 1) * Uu * Uu];
// pre-split MLP weight Wm1[0:256,:] -> [n=128][k=256] K-major hi/lo
__device__ __nv_bfloat16 g_Wm1H[128 * Uu];
__device__ __nv_bfloat16 g_Wm1L[128 * Uu];
// pre-split node weights: 14 slots (l*4 + {W1,W2,Ws,Wt}; 12=WsL, 13=WtL)
__device__ __nv_bfloat16 g_WnH[14 * Uu * Uu];
__device__ __nv_bfloat16 g_WnL[14 * Uu * Uu];

// ---------------- helpers ----------------------------------------------------
__device__ __forceinline__ uint32_t smem_u32(const void* p) {
    uint32_t a;
    asm("{ .reg .u64 t; cvta.to.shared.u64 t, %1; cvt.u32.u64 %0, t; }"
        : "=r"(a) : "l"(p));
    return a;
}

__device__ __forceinline__ void cp16(uint32_t s, const void* g) {
    asm volatile("cp.async.cg.shared.global [%0], [%1], 16;" :: "r"(s), "l"(g));
}
#define CP_COMMIT() asm volatile("cp.async.commit_group;" ::: "memory")
#define CP_WAIT0()  asm volatile("cp.async.wait_group 0;" ::: "memory")

__device__ __forceinline__ void split2(float a, float b, uint32_t& h, uint32_t& l)
{
    __nv_bfloat16 ha = __float2bfloat16(a);
    __nv_bfloat16 hb = __float2bfloat16(b);
    __nv_bfloat162 hp;
    hp.x = ha; hp.y = hb;
    h = *reinterpret_cast<uint32_t*>(&hp);
    __nv_bfloat162 lp;
    lp.x = __float2bfloat16(a - __bfloat162float(ha));
    lp.y = __float2bfloat16(b - __bfloat162float(hb));
    l = *reinterpret_cast<uint32_t*>(&lp);
}

__device__ __forceinline__ void mma16816(float* c, const uint32_t* a,
                                         const uint32_t* b)
{
    asm volatile(
        "mma.sync.aligned.m16n8k16.row.col.f32.bf16.bf16.f32 "
        "{%0,%1,%2,%3}, {%4,%5,%6,%7}, {%8,%9}, {%0,%1,%2,%3};"
        : "+f"(c[0]), "+f"(c[1]), "+f"(c[2]), "+f"(c[3])
        : "r"(a[0]), "r"(a[1]), "r"(a[2]), "r"(a[3]), "r"(b[0]), "r"(b[1]));
}

// SMEM row stride 40 bf16 (80 B): conflict-free frag LDS (proven in R9).
#define SLD 40
#define TILE_B 10240            // 128 * 40 * 2 bytes
#define BUF_B  (4 * TILE_B)     // Ah, Al, Bh, Bl per buffer
#define SMEMB  (2 * BUF_B + 1024)

// ---- double-buffered 3-pass mainloop (row-clamped):
//      acc += Ah@Bh^T + Ah@Bl^T + Al@Bh^T
__device__ __forceinline__ void mma_mainloop_db(
    const float* __restrict__ A,
    const __nv_bfloat16* __restrict__ Bh, const __nv_bfloat16* __restrict__ Bl,
    int row0, int col0, int Mrows, unsigned char* sm, uint32_t smb,
    float acc[2][8][4])
{
    const int tid = threadIdx.x;
    const int wid = tid >> 5;
    const int lane = tid & 31;
    const int g = lane >> 2;
    const int tg = lane & 3;
    const int m0 = (wid & 3) * 32;
    const int n0 = (wid >> 2) * 64;
    const int frow = tid >> 1;
    const int fkh = (tid & 1) * 16;

    int agrow = row0 + frow;
    if (agrow >= Mrows) agrow = Mrows - 1;
    const float4* arow = (const float4*)(A + (size_t)agrow * Uu);
    const __nv_bfloat16* bhrow = Bh + (size_t)(col0 + frow) * Uu;
    const __nv_bfloat16* blrow = Bl + (size_t)(col0 + frow) * Uu;

    const uint32_t sdst = smb + frow * 80 + fkh * 2;
    const uint32_t arow_off = frow * 80 + fkh * 2;

    float4 aPF[4];
#pragma unroll
    for (int q = 0; q < 4; q++) aPF[q] = arow[(fkh >> 2) + q];
    {
        uint32_t db = sdst + 2 * TILE_B;
        cp16(db,      bhrow + fkh);
        cp16(db + 16, bhrow + fkh + 8);
        uint32_t dl = db + TILE_B;
        cp16(dl,      blrow + fkh);
        cp16(dl + 16, blrow + fkh + 8);
        CP_COMMIT();
    }
#pragma unroll
    for (int q = 0; q < 4; q++) {
        uint32_t h0, l0, h1, l1;
        split2(aPF[q].x, aPF[q].y, h0, l0);
        split2(aPF[q].z, aPF[q].w, h1, l1);
        *(uint32_t*)(sm + arow_off + (4 * q) * 2)              = h0;
        *(uint32_t*)(sm + arow_off + (4 * q + 2) * 2)          = h1;
        *(uint32_t*)(sm + TILE_B + arow_off + (4 * q) * 2)     = l0;
        *(uint32_t*)(sm + TILE_B + arow_off + (4 * q + 2) * 2) = l1;
    }
    CP_WAIT0();
    __syncthreads();

    for (int kc = 0; kc < 8; kc++) {
        const int cur = kc & 1;
        if (kc < 7) {
            const int nk = (kc + 1) * 32;
#pragma unroll
            for (int q = 0; q < 4; q++) aPF[q] = arow[((nk + fkh) >> 2) + q];
            uint32_t db = sdst + (cur ^ 1) * BUF_B + 2 * TILE_B;
            cp16(db,      bhrow + nk + fkh);
            cp16(db + 16, bhrow + nk + fkh + 8);
            uint32_t dl = db + TILE_B;
            cp16(dl,      blrow + nk + fkh);
            cp16(dl + 16, blrow + nk + fkh + 8);
            CP_COMMIT();
        }

        const __nv_bfloat16 (*ApH)[SLD] =
            (const __nv_bfloat16 (*)[SLD])(sm + cur * BUF_B);
        const __nv_bfloat16 (*ApL)[SLD] =
            (const __nv_bfloat16 (*)[SLD])(sm + cur * BUF_B + TILE_B);
        const __nv_bfloat16 (*BpH)[SLD] =
            (const __nv_bfloat16 (*)[SLD])(sm + cur * BUF_B + 2 * TILE_B);
        const __nv_bfloat16 (*BpL)[SLD] =
            (const __nv_bfloat16 (*)[SLD])(sm + cur * BUF_B + 3 * TILE_B);

#pragma unroll
        for (int pass = 0; pass < 3; pass++) {
            const __nv_bfloat16 (*Ap)[SLD] = (pass == 2) ? ApL : ApH;
            const __nv_bfloat16 (*Bp)[SLD] = (pass == 1) ? BpL : BpH;
#pragma unroll
            for (int ks = 0; ks < 2; ks++) {
                const int kb = ks * 16 + tg * 2;
                uint32_t a[2][4], b[8][2];
#pragma unroll
                for (int mt = 0; mt < 2; mt++) {
                    int mr = m0 + mt * 16 + g;
                    a[mt][0] = *(const uint32_t*)&Ap[mr][kb];
                    a[mt][1] = *(const uint32_t*)&Ap[mr + 8][kb];
                    a[mt][2] = *(const uint32_t*)&Ap[mr][kb + 8];
                    a[mt][3] = *(const uint32_t*)&Ap[mr + 8][kb + 8];
                }
#pragma unroll
                for (int nt = 0; nt < 8; nt++) {
                    int nr = n0 + nt * 8 + g;
                    b[nt][0] = *(const uint32_t*)&Bp[nr][kb];
                    b[nt][1] = *(const uint32_t*)&Bp[nr][kb + 8];
                }
#pragma unroll
                for (int mt = 0; mt < 2; mt++)
#pragma unroll
                    for (int nt = 0; nt < 8; nt++)
                        mma16816(acc[mt][nt], a[mt], b[nt]);
            }
        }

        if (kc < 7) {
            unsigned char* an = sm + (cur ^ 1) * BUF_B;
#pragma unroll
            for (int q = 0; q < 4; q++) {
                uint32_t h0, l0, h1, l1;
                split2(aPF[q].x, aPF[q].y, h0, l0);
                split2(aPF[q].z, aPF[q].w, h1, l1);
                *(uint32_t*)(an + arow_off + (4 * q) * 2)              = h0;
                *(uint32_t*)(an + arow_off + (4 * q + 2) * 2)          = h1;
                *(uint32_t*)(an + TILE_B + arow_off + (4 * q) * 2)     = l0;
                *(uint32_t*)(an + TILE_B + arow_off + (4 * q + 2) * 2) = l1;
            }
            CP_WAIT0();
        }
        __syncthreads();
    }
}

// ---- tensor-core fused edge update:
//   Enew = Eold + relu(Eold@We + xWs[src] + xWt[dst] + be)
__global__ void __launch_bounds__(256) k_edge_mma(
    const float* __restrict__ Eold,
    const __nv_bfloat16* __restrict__ Wh, const __nv_bfloat16* __restrict__ Wl,
    const float* __restrict__ bel,
    const float* __restrict__ xWs, const float* __restrict__ xWt,
    const int* __restrict__ src, const int* __restrict__ dst,
    float* __restrict__ Enew)
{
    extern __shared__ __align__(16) unsigned char sm[];
    const uint32_t smb = smem_u32(sm);
    int* src_s = (int*)(sm + 2 * BUF_B);
    int* dst_s = src_s + BM;

    const int tid = threadIdx.x;
    const int wid = tid >> 5;
    const int lane = tid & 31;
    const int g = lane >> 2;
    const int tg = lane & 3;
    const int row0 = blockIdx.x * BM;
    const int col0 = blockIdx.y * BN;
    const int m0 = (wid & 3) * 32;
    const int n0 = (wid >> 2) * 64;

    if (tid < BM) {
        src_s[tid] = src[row0 + tid];
        dst_s[tid] = dst[row0 + tid];
    }

    float acc[2][8][4];
#pragma unroll
    for (int mt = 0; mt < 2; mt++)
#pragma unroll
        for (int nt = 0; nt < 8; nt++)
#pragma unroll
            for (int q = 0; q < 4; q++) acc[mt][nt][q] = 0.f;

    mma_mainloop_db(Eold, Wh, Wl, row0, col0, Ee, sm, smb, acc);

    // ---- fused epilogue ----
#pragma unroll
    for (int mt = 0; mt < 2; mt++) {
#pragma unroll
        for (int h = 0; h < 2; h++) {
            int lrow = m0 + mt * 16 + g + h * 8;
            int r = row0 + lrow;
            int s = src_s[lrow];
            int d = dst_s[lrow];
            const float* wsp = xWs + (size_t)s * Uu + col0 + n0;
            const float* wtp = xWt + (size_t)d * Uu + col0 + n0;
            const float* eop = Eold + (size_t)r * Uu + col0 + n0;
            const float* bbp = bel + col0 + n0;
            float* outp = Enew + (size_t)r * Uu + col0 + n0;
#pragma unroll
            for (int nt = 0; nt < 8; nt++) {
                int c = nt * 8 + tg * 2;
                float2 ws = *(const float2*)(wsp + c);
                float2 wt = *(const float2*)(wtp + c);
                float2 eo = *(const float2*)(eop + c);
                float2 bb = *(const float2*)(bbp + c);
                float a0 = acc[mt][nt][h * 2 + 0];
                float a1 = acc[mt][nt][h * 2 + 1];
                float2 v;
                v.x = eo.x + fmaxf(a0 + ws.x + wt.x + bb.x, 0.f);
                v.y = eo.y + fmaxf(a1 + ws.y + wt.y + bb.y, 0.f);
                *(float2*)(outp + c) = v;
            }
        }
    }
}

// ---- CSR build kernels ------------------------------------------------------
__global__ void k_zero_cnt()
{
    int t = blockIdx.x * blockDim.x + threadIdx.x;
    if (t < Nn) g_cnt[t] = 0;
}

__global__ void k_count(const int* __restrict__ dst)
{
    int t = blockIdx.x * blockDim.x + threadIdx.x;
    if (t < Ee) atomicAdd(&g_cnt[dst[t]], 1);
}

__global__ void k_scan()  // 1 block, 1024 threads, exclusive scan of g_cnt
{
    __shared__ int part[1024];
    const int tid = threadIdx.x;
    const int PER = 10;  // 1024*10 >= 10000
    int base = tid * PER;
    int lo[PER];
    int sum = 0;
#pragma unroll
    for (int q = 0; q < PER; q++) {
        int idx = base + q;
        int v = (idx < Nn) ? g_cnt[idx] : 0;
        lo[q] = sum;
        sum += v;
    }
    part[tid] = sum;
    __syncthreads();
    for (int off = 1; off < 1024; off <<= 1) {
        int v = 0;
        if (tid >= off) v = part[tid - off];
        __syncthreads();
        if (tid >= off) part[tid] += v;
        __syncthreads();
    }
    int chunk = (tid > 0) ? part[tid - 1] : 0;
#pragma unroll
    for (int q = 0; q < PER; q++) {
        int idx = base + q;
        if (idx < Nn) {
            int r = chunk + lo[q];
            g_rowptr[idx] = r;
            g_off[idx] = r;
        }
    }
    if (tid == 1023) g_rowptr[Nn] = part[1023];
}

__global__ void k_scatter(const int* __restrict__ dst)
{
    int t = blockIdx.x * blockDim.x + threadIdx.x;
    if (t >= Ee) return;
    int p = atomicAdd(&g_off[dst[t]], 1);
    g_perm[p] = t;
}

// ---- CSR message pass + fused node update:
//   x[d] += relu(xW1[d] + sum_{e: dst=d} sigmoid(e)*xW2[src[e]])
__global__ void __launch_bounds__(256) k_msg_fused(
    const float* __restrict__ e, const float* __restrict__ xW2,
    const float* __restrict__ xW1, const int* __restrict__ src,
    float* __restrict__ x)
{
    const int d = blockIdx.x;
    const int c = threadIdx.x;
    const int rp = g_rowptr[d];
    const int re = g_rowptr[d + 1];
    float sum = 0.f;
    for (int j = rp; j < re; j++) {
        int i = __ldg(&g_perm[j]);
        int s = __ldg(&src[i]);
        float ev = __ldg(e + (size_t)i * Uu + c);
        float xv = __ldg(xW2 + (size_t)s * Uu + c);
        sum += xv / (1.f + __expf(-ev));
    }
    size_t o = (size_t)d * Uu + c;
    x[o] += fmaxf(xW1[o] + sum, 0.f);
}

// ---- tensor-core node GEMMs: C[z] = x @ W[z] (+ bias[z]) -------------------
struct NodePtrs {
    const __nv_bfloat16* Bh[4];
    const __nv_bfloat16* Bl[4];
    const float* bias[4];
    float* C[4];
};

__global__ void __launch_bounds__(256) k_node_mma(const float* __restrict__ A,
                                                  NodePtrs p)
{
    extern __shared__ __align__(16) unsigned char sm[];
    const uint32_t smb = smem_u32(sm);

    const int tid = threadIdx.x;
    const int wid = tid >> 5;
    const int lane = tid & 31;
    const int g = lane >> 2;
    const int tg = lane & 3;
    const int z = blockIdx.z;
    const int row0 = blockIdx.x * BM;
    const int col0 = blockIdx.y * BN;
    const int m0 = (wid & 3) * 32;
    const int n0 = (wid >> 2) * 64;

    float acc[2][8][4];
#pragma unroll
    for (int mt = 0; mt < 2; mt++)
#pragma unroll
        for (int nt = 0; nt < 8; nt++)
#pragma unroll
            for (int q = 0; q < 4; q++) acc[mt][nt][q] = 0.f;

    mma_mainloop_db(A, p.Bh[z], p.Bl[z], row0, col0, Nn, sm, smb, acc);

    const float* bias = p.bias[z];
    float* C = p.C[z];
#pragma unroll
    for (int mt = 0; mt < 2; mt++) {
#pragma unroll
        for (int h = 0; h < 2; h++) {
            int r = row0 + m0 + mt * 16 + g + h * 8;
            if (r >= Nn) continue;
            float* outp = C + (size_t)r * Uu + col0 + n0;
            const float* bbp = bias ? bias + col0 + n0 : nullptr;
#pragma unroll
            for (int nt = 0; nt < 8; nt++) {
                int c = nt * 8 + tg * 2;
                float2 v;
                v.x = acc[mt][nt][h * 2 + 0];
                v.y = acc[mt][nt][h * 2 + 1];
                if (bias) {
                    float2 bb = *(const float2*)(bbp + c);
                    v.x += bb.x;
                    v.y += bb.y;
                }
                *(float2*)(outp + c) = v;
            }
        }
    }
}

// ---- tensor-core MLP head: out = prelu([e|a]@Wm1 + bm1) @ Wm2 + bm2 --------
__global__ void __launch_bounds__(256) k_mlp_mma(
    const float* __restrict__ Efin, const float* __restrict__ ain,
    const __nv_bfloat16* __restrict__ W1h, const __nv_bfloat16* __restrict__ W1l,
    const float* __restrict__ Wm1, const float* __restrict__ bm1,
    const float* __restrict__ alpha, const float* __restrict__ Wm2,
    const float* __restrict__ bm2, float* __restrict__ outp)
{
    extern __shared__ __align__(16) unsigned char sm[];
    const uint32_t smb = smem_u32(sm);
    float* red = (float*)(sm + 2 * BUF_B);  // [128][2]

    const int tid = threadIdx.x;
    const int wid = tid >> 5;
    const int lane = tid & 31;
    const int g = lane >> 2;
    const int tg = lane & 3;
    const int row0 = blockIdx.x * BM;
    const int m0 = (wid & 3) * 32;
    const int n0 = (wid >> 2) * 64;

    float acc[2][8][4];
#pragma unroll
    for (int mt = 0; mt < 2; mt++)
#pragma unroll
        for (int nt = 0; nt < 8; nt++)
#pragma unroll
            for (int q = 0; q < 4; q++) acc[mt][nt][q] = 0.f;

    mma_mainloop_db(Efin, W1h, W1l, row0, 0, Ee, sm, smb, acc);

    const float al = alpha[0];
    const float* wlp = Wm1 + 256 * 128;
#pragma unroll
    for (int mt = 0; mt < 2; mt++) {
#pragma unroll
        for (int h = 0; h < 2; h++) {
            int lrow = m0 + mt * 16 + g + h * 8;
            float a = ain[row0 + lrow];
            float part = 0.f;
#pragma unroll
            for (int nt = 0; nt < 8; nt++) {
                int c = n0 + nt * 8 + tg * 2;
                float2 wl = *(const float2*)(wlp + c);
                float2 b1 = *(const float2*)(bm1 + c);
                float2 w2 = *(const float2*)(Wm2 + c);
                float h0 = acc[mt][nt][h * 2 + 0] + a * wl.x + b1.x;
                float h1 = acc[mt][nt][h * 2 + 1] + a * wl.y + b1.y;
                h0 = (h0 > 0.f) ? h0 : al * h0;
                h1 = (h1 > 0.f) ? h1 : al * h1;
                part = fmaf(h0, w2.x, part);
                part = fmaf(h1, w2.y, part);
            }
            part += __shfl_xor_sync(0xFFFFFFFFu, part, 1);
            part += __shfl_xor_sync(0xFFFFFFFFu, part, 2);
            if (tg == 0) red[lrow * 2 + (wid >> 2)] = part;
        }
    }
    __syncthreads();
    if (tid < BM)
        outp[row0 + tid] = red[tid * 2] + red[tid * 2 + 1] + bm2[0];
}

// ---- weight pre-split kernels ----------------------------------------------
__global__ void k_prep_we(const float* __restrict__ We)
{
    int t = blockIdx.x * blockDim.x + threadIdx.x;
    if (t >= (Ll + 1) * Uu * Uu) return;
    int l = t >> 16;
    int n = (t >> 8) & 255;
    int k = t & 255;
    float w = We[(size_t)l * Uu * Uu + k * Uu + n];
    __nv_bfloat16 h = __float2bfloat16(w);
    g_WeH[t] = h;
    g_WeL[t] = __float2bfloat16(w - __bfloat162float(h));
}

__global__ void k_prep_wm1(const float* __restrict__ Wm1)
{
    int t = blockIdx.x * blockDim.x + threadIdx.x;
    if (t >= 128 * Uu) return;
    int n = t >> 8;
    int k = t & 255;
    float w = Wm1[k * 128 + n];
    __nv_bfloat16 h = __float2bfloat16(w);
    g_Wm1H[t] = h;
    g_Wm1L[t] = __float2bfloat16(w - __bfloat162float(h));
}

__global__ void k_prep_wn(const float* __restrict__ W1,
                          const float* __restrict__ W2,
                          const float* __restrict__ Ws,
                          const float* __restrict__ Wt)
{
    int t = blockIdx.x * blockDim.x + threadIdx.x;
    if (t >= 14 * Uu * Uu) return;
    int slot = t >> 16;
    int n = (t >> 8) & 255;
    int k = t & 255;
    const float* base;
    if (slot < 12) {
        int l = slot >> 2;
        int which = slot & 3;
        base = (which == 0 ? W1 : which == 1 ? W2 : which == 2 ? Ws : Wt) +
               (size_t)l * Uu * Uu;
    } else {
        base = (slot == 12 ? Ws : Wt) + (size_t)Ll * Uu * Uu;
    }
    float w = base[k * Uu + n];
    __nv_bfloat16 h = __float2bfloat16(w);
    g_WnH[t] = h;
    g_WnL[t] = __float2bfloat16(w - __bfloat162float(h));
}

// ---------------- elementwise kernels ----------------------------------------
__global__ void k_init_x(const float* __restrict__ pos,
                         const float* __restrict__ Wp,
                         const float* __restrict__ bp)
{
    int t = blockIdx.x * blockDim.x + threadIdx.x;
    if (t >= Nn * Uu) return;
    int i = t >> 8, j = t & 255;
    g_x[t] = fmaf(pos[2 * i], Wp[j], fmaf(pos[2 * i + 1], Wp[Uu + j], bp[j]));
}

__global__ void k_init_e(const float* __restrict__ a,
                         const float* __restrict__ Wa,
                         const float* __restrict__ ba,
                         float* __restrict__ e)
{
    int t = blockIdx.x * blockDim.x + threadIdx.x;
    if (t >= Ee * (Uu / 4)) return;
    int i = t >> 6;
    int j = (t & 63) << 2;
    float av = a[i];
    float4 w = *(const float4*)(Wa + j);
    float4 b = *(const float4*)(ba + j);
    float4 v;
    v.x = fmaf(av, w.x, b.x);
    v.y = fmaf(av, w.y, b.y);
    v.z = fmaf(av, w.z, b.z);
    v.w = fmaf(av, w.w, b.w);
    *(float4*)(e + (size_t)i * Uu + j) = v;
}

// ---------------- host driver ------------------------------------------------
extern "C" void kernel_launch(void* const* d_in, const int* in_sizes, int n_in,
                              void* d_out, int out_size)
{
    const float* pos   = (const float*)d_in[0];
    const float* ain   = (const float*)d_in[1];
    const int*   eidx  = (const int*)d_in[2];
    const float* Wp    = (const float*)d_in[3];
    const float* bp    = (const float*)d_in[4];
    const float* Wa    = (const float*)d_in[5];
    const float* ba    = (const float*)d_in[6];
    const float* W1    = (const float*)d_in[7];
    const float* b1    = (const float*)d_in[8];
    const float* W2    = (const float*)d_in[9];
    const float* b2    = (const float*)d_in[10];
    const float* We    = (const float*)d_in[11];
    const float* be    = (const float*)d_in[12];
    const float* Ws    = (const float*)d_in[13];
    const float* Wt    = (const float*)d_in[14];
    const float* Wm1   = (const float*)d_in[15];
    const float* bm1   = (const float*)d_in[16];
    const float* alpha = (const float*)d_in[17];
    const float* Wm2   = (const float*)d_in[18];
    const float* bm2   = (const float*)d_in[19];
    float* outp = (float*)d_out;

    const int* src = eidx;
    const int* dst = eidx + Ee;

    float *px, *pxW1, *pxW2, *pxWs, *pxWt, *pe0, *pe1;
    __nv_bfloat16 *pWH, *pWL, *pM1H, *pM1L, *pWnH, *pWnL;
    cudaGetSymbolAddress((void**)&px,   g_x);
    cudaGetSymbolAddress((void**)&pxW1, g_xW1);
    cudaGetSymbolAddress((void**)&pxW2, g_xW2);
    cudaGetSymbolAddress((void**)&pxWs, g_xWs);
    cudaGetSymbolAddress((void**)&pxWt, g_xWt);
    cudaGetSymbolAddress((void**)&pe0,  g_e0);
    cudaGetSymbolAddress((void**)&pe1,  g_e1);
    cudaGetSymbolAddress((void**)&pWH,  g_WeH);
    cudaGetSymbolAddress((void**)&pWL,  g_WeL);
    cudaGetSymbolAddress((void**)&pM1H, g_Wm1H);
    cudaGetSymbolAddress((void**)&pM1L, g_Wm1L);
    cudaGetSymbolAddress((void**)&pWnH, g_WnH);
    cudaGetSymbolAddress((void**)&pWnL, g_WnL);

    cudaFuncSetAttribute(k_edge_mma, cudaFuncAttributeMaxDynamicSharedMemorySize,
                         SMEMB);
    cudaFuncSetAttribute(k_node_mma, cudaFuncAttributeMaxDynamicSharedMemorySize,
                         SMEMB);
    cudaFuncSetAttribute(k_mlp_mma, cudaFuncAttributeMaxDynamicSharedMemorySize,
                         SMEMB);

    const int nodeRowBlocks = (Nn + BM - 1) / BM;  // 79

    k_init_x<<<(Nn * Uu + 255) / 256, 256>>>(pos, Wp, bp);
    k_init_e<<<(Ee * (Uu / 4) + 255) / 256, 256>>>(ain, Wa, ba, pe0);
    k_prep_we<<<((Ll + 1) * Uu * Uu + 255) / 256, 256>>>(We);
    k_prep_wm1<<<(128 * Uu + 255) / 256, 256>>>(Wm1);
    k_prep_wn<<<(14 * Uu * Uu + 255) / 256, 256>>>(W1, W2, Ws, Wt);

    // CSR build (once per launch; reused across layers)
    k_zero_cnt<<<(Nn + 255) / 256, 256>>>();
    k_count<<<(Ee + 255) / 256, 256>>>(dst);
    k_scan<<<1, 1024>>>();
    k_scatter<<<(Ee + 255) / 256, 256>>>(dst);

    float* ecur = pe0;
    float* enxt = pe1;

    for (int l = 0; l < Ll; l++) {
        NodePtrs p;
        const int s0 = l * 4;
        for (int z = 0; z < 4; z++) {
            p.Bh[z] = pWnH + (size_t)(s0 + z) * Uu * Uu;
            p.Bl[z] = pWnL + (size_t)(s0 + z) * Uu * Uu;
        }
        p.bias[0] = b1 + (size_t)l * Uu;
        p.bias[1] = b2 + (size_t)l * Uu;
        p.bias[2] = nullptr;
        p.bias[3] = nullptr;
        p.C[0] = pxW1; p.C[1] = pxW2; p.C[2] = pxWs; p.C[3] = pxWt;
        k_node_mma<<<dim3(nodeRowBlocks, 2, 4), 256, SMEMB>>>(px, p);

        k_edge_mma<<<dim3(Ee / BM, 2), 256, SMEMB>>>(
            ecur, pWH + (size_t)l * Uu * Uu, pWL + (size_t)l * Uu * Uu,
            be + (size_t)l * Uu, pxWs, pxWt, src, dst, enxt);

        // CSR message pass + node update (reads old e; x updated in place)
        k_msg_fused<<<Nn, 256>>>(ecur, pxW2, pxW1, src, px);

        float* tmp = ecur; ecur = enxt; enxt = tmp;
    }

    // final edge update (l = L): no msg
    {
        NodePtrs p;
        p.Bh[0] = pWnH + (size_t)12 * Uu * Uu;
        p.Bl[0] = pWnL + (size_t)12 * Uu * Uu;
        p.Bh[1] = pWnH + (size_t)13 * Uu * Uu;
        p.Bl[1] = pWnL + (size_t)13 * Uu * Uu;
        p.Bh[2] = p.Bh[0]; p.Bl[2] = p.Bl[0];
        p.Bh[3] = p.Bh[0]; p.Bl[3] = p.Bl[0];
        p.bias[0] = nullptr; p.bias[1] = nullptr;
        p.bias[2] = nullptr; p.bias[3] = nullptr;
        p.C[0] = pxWs; p.C[1] = pxWt; p.C[2] = pxWs; p.C[3] = pxWs;
        k_node_mma<<<dim3(nodeRowBlocks, 2, 2), 256, SMEMB>>>(px, p);

        k_edge_mma<<<dim3(Ee / BM, 2), 256, SMEMB>>>(
            ecur, pWH + (size_t)Ll * Uu * Uu, pWL + (size_t)Ll * Uu * Uu,
            be + (size_t)Ll * Uu, pxWs, pxWt, src, dst, enxt);
        float* tmp = ecur; ecur = enxt; enxt = tmp;
    }

    k_mlp_mma<<<Ee / BM, 256, SMEMB>>>(ecur, ain, pM1H, pM1L, Wm1, bm1,
                                       alpha, Wm2, bm2, outp);
}